// round 3
// baseline (speedup 1.0000x reference)
#include <cuda_runtime.h>
#include <cuda_fp16.h>
#include <cstdint>

// ---------------- Problem dims (fixed by the dataset) ----------------
#define D_DIM 4096
#define I_DIM 11008
#define M_DIM 8192          // 4 * 2048 tokens

// ---------------- Scratch (device globals: allocation-free) ----------
__device__ __half g_xh[(size_t)M_DIM * D_DIM];     //  64 MB  x in fp16 [M, D]
__device__ __half g_Wg[(size_t)I_DIM * D_DIM];     //  90 MB  gate W^T [I, D] (K-major)
__device__ __half g_Wu[(size_t)I_DIM * D_DIM];     //  90 MB  up   W^T [I, D]
__device__ __half g_Wd[(size_t)D_DIM * I_DIM];     //  90 MB  down W^T [D, I]
__device__ __half g_t1[(size_t)M_DIM * I_DIM];     // 176 MB  gate pre-activation fp16
__device__ __half g_h [(size_t)M_DIM * I_DIM];     // 176 MB  h = silu(gate)*up [M, I]

// ---------------- helpers ----------------------------------------
__device__ __forceinline__ uint32_t smem_u32(const void* p) {
    uint32_t a;
    asm("{ .reg .u64 t; cvta.to.shared.u64 t, %1; cvt.u32.u64 %0, t; }" : "=r"(a) : "l"(p));
    return a;
}
__device__ __forceinline__ void cp16(uint32_t s, const void* g) {
    asm volatile("cp.async.cg.shared.global [%0], [%1], 16;" :: "r"(s), "l"(g));
}
#define CP_COMMIT() asm volatile("cp.async.commit_group;" ::: "memory")
#define CP_WAIT1()  asm volatile("cp.async.wait_group 1;" ::: "memory")

#define LDSM_X4(r, addr) \
    asm volatile("ldmatrix.sync.aligned.m8n8.x4.shared.b16 {%0,%1,%2,%3}, [%4];" \
        : "=r"((r)[0]), "=r"((r)[1]), "=r"((r)[2]), "=r"((r)[3]) : "r"(addr))

__device__ __forceinline__ void mma16816(float* c, const uint32_t* a,
                                         uint32_t b0, uint32_t b1) {
    asm volatile(
        "mma.sync.aligned.m16n8k16.row.col.f32.f16.f16.f32 "
        "{%0,%1,%2,%3}, {%4,%5,%6,%7}, {%8,%9}, {%0,%1,%2,%3};"
        : "+f"(c[0]), "+f"(c[1]), "+f"(c[2]), "+f"(c[3])
        : "r"(a[0]), "r"(a[1]), "r"(a[2]), "r"(a[3]), "r"(b0), "r"(b1));
}

// ---------------- Prepass kernels -------------------------------------
__global__ void cvt_x_kernel(const float* __restrict__ x) {
    size_t i = ((size_t)blockIdx.x * blockDim.x + threadIdx.x) * 4;
    float4 v = *(const float4*)(x + i);
    __half2* o = (__half2*)(g_xh + i);
    o[0] = __floats2half2_rn(v.x, v.y);
    o[1] = __floats2half2_rn(v.z, v.w);
}

// q:[K,N] int32 (0..15), s/z:[K/128,N].  Out: Wt[N,K] fp16, Wt[n,k] = (q[k,n]-8)*s+z
__global__ void dequant_t_kernel(const int* __restrict__ q, const float* __restrict__ s,
                                 const float* __restrict__ z, __half* __restrict__ Wt,
                                 int K, int N) {
    __shared__ __half tile[32][33];
    int n0 = blockIdx.x * 32, k0 = blockIdx.y * 32;
    int tx = threadIdx.x, ty = threadIdx.y;          // block (32, 8)
    int n = n0 + tx;
    int grp = k0 >> 7;                               // whole 32-row tile in one group
    float sv = s[(size_t)grp * N + n];
    float zv = z[(size_t)grp * N + n];
#pragma unroll
    for (int i = 0; i < 4; i++) {
        int k = k0 + ty + i * 8;
        int qv = q[(size_t)k * N + n];
        tile[ty + i * 8][tx] = __float2half((float)(qv - 8) * sv + zv);
    }
    __syncthreads();
#pragma unroll
    for (int i = 0; i < 4; i++) {
        int nn = n0 + ty + i * 8;
        Wt[(size_t)nn * K + k0 + tx] = tile[tx][ty + i * 8];
    }
}

// ---------------- HMMA GEMM ----------------------------------------
// C[M,N] = A[M,K] @ B[N,K]^T.  A,B fp16 K-major.  128x128 CTA tile, BK=32,
// 256 threads = 8 warps (4 along M x 2 along N), warp tile 32x64.
// MODE 0: store fp16 raw (gate).  MODE 1: h = silu(aux)*acc, fp16 (up+silu).
// MODE 2: store fp32 (down output).
static constexpr int STAGE_B  = 20480;   // A 128*80 + B 128*80
static constexpr int GEMM_SMEM = 3 * STAGE_B;  // 61440

template <int MODE>
__global__ void __launch_bounds__(256, 1)
gemm_hmma(const __half* __restrict__ Ag, const __half* __restrict__ Bg,
          void* __restrict__ Cg, const __half* __restrict__ aux,
          int K, int N) {
    extern __shared__ char smem[];
    uint32_t sb = smem_u32(smem);
    int tid = threadIdx.x;
    int lane = tid & 31, warp = tid >> 5;
    int wm = (warp & 3) * 32;        // warp M offset in tile
    int wn = (warp >> 2) * 64;       // warp N offset in tile
    int m0 = blockIdx.x * 128;
    int n0 = blockIdx.y * 128;

    const __half* gA = Ag + (size_t)m0 * K;
    const __half* gB = Bg + (size_t)n0 * K;

    auto load_stage = [&](int s, int k0) {
        uint32_t sa = sb + (uint32_t)s * STAGE_B;
#pragma unroll
        for (int i = 0; i < 2; i++) {
            int id = tid + i * 256;
            int r = id >> 2, c = id & 3;
            cp16(sa + r * 80 + c * 16, gA + (size_t)r * K + k0 + c * 8);
        }
#pragma unroll
        for (int i = 0; i < 2; i++) {
            int id = tid + i * 256;
            int r = id >> 2, c = id & 3;
            cp16(sa + 10240 + r * 80 + c * 16, gB + (size_t)r * K + k0 + c * 8);
        }
    };

    float acc[2][8][4];
#pragma unroll
    for (int i = 0; i < 2; i++)
#pragma unroll
        for (int j = 0; j < 8; j++)
#pragma unroll
            for (int l = 0; l < 4; l++) acc[i][j][l] = 0.0f;

    load_stage(0, 0);  CP_COMMIT();
    load_stage(1, 32); CP_COMMIT();

    int nk = K / 32;
#pragma unroll 1
    for (int k = 0; k < nk; k++) {
        CP_WAIT1();
        __syncthreads();
        if (k + 2 < nk) load_stage((k + 2) % 3, (k + 2) * 32);
        CP_COMMIT();

        uint32_t sa = sb + (uint32_t)(k % 3) * STAGE_B;
        uint32_t sB = sa + 10240;
#pragma unroll
        for (int ks = 0; ks < 2; ks++) {
            uint32_t a[2][4], b[4][4];
#pragma unroll
            for (int mi = 0; mi < 2; mi++) {
                uint32_t addr = sa + (uint32_t)((wm + mi * 16 + (lane & 15)) * 80
                              + (ks * 16 + (lane >> 4) * 8) * 2);
                LDSM_X4(a[mi], addr);
            }
#pragma unroll
            for (int bi = 0; bi < 4; bi++) {
                int n = wn + bi * 16 + (lane & 7) + ((lane >> 4) & 1) * 8;
                int kk = ks * 16 + ((lane >> 3) & 1) * 8;
                uint32_t addr = sB + (uint32_t)(n * 80 + kk * 2);
                LDSM_X4(b[bi], addr);
            }
#pragma unroll
            for (int mi = 0; mi < 2; mi++)
#pragma unroll
                for (int bi = 0; bi < 4; bi++) {
                    mma16816(acc[mi][2 * bi],     a[mi], b[bi][0], b[bi][1]);
                    mma16816(acc[mi][2 * bi + 1], a[mi], b[bi][2], b[bi][3]);
                }
        }
    }

    // ---- epilogue ----
    int r0 = m0 + wm + (lane >> 2);
    int c0 = n0 + wn + (lane & 3) * 2;
#pragma unroll
    for (int mi = 0; mi < 2; mi++) {
#pragma unroll
        for (int hi = 0; hi < 2; hi++) {
            int row = r0 + mi * 16 + hi * 8;
#pragma unroll
            for (int ni = 0; ni < 8; ni++) {
                int col = c0 + ni * 8;
                float v0 = acc[mi][ni][2 * hi], v1 = acc[mi][ni][2 * hi + 1];
                if (MODE == 0) {
                    *(__half2*)((__half*)Cg + (size_t)row * N + col) =
                        __floats2half2_rn(v0, v1);
                } else if (MODE == 1) {
                    __half2 gh = *(const __half2*)(aux + (size_t)row * N + col);
                    float g0 = __half2float(gh.x), g1 = __half2float(gh.y);
                    float h0 = g0 / (1.0f + __expf(-g0)) * v0;
                    float h1 = g1 / (1.0f + __expf(-g1)) * v1;
                    *(__half2*)((__half*)Cg + (size_t)row * N + col) =
                        __floats2half2_rn(h0, h1);
                } else {
                    *(float2*)((float*)Cg + (size_t)row * N + col) =
                        make_float2(v0, v1);
                }
            }
        }
    }
}

// ---------------- Launch ----------------------------------------------
extern "C" void kernel_launch(void* const* d_in, const int* in_sizes, int n_in,
                              void* d_out, int out_size) {
    (void)in_sizes; (void)n_in; (void)out_size;
    const float* x  = (const float*)d_in[0];
    const int*   gq = (const int*)  d_in[1];
    const float* gs = (const float*)d_in[2];
    const float* gz = (const float*)d_in[3];
    const int*   uq = (const int*)  d_in[4];
    const float* us = (const float*)d_in[5];
    const float* uz = (const float*)d_in[6];
    const int*   dq = (const int*)  d_in[7];
    const float* ds = (const float*)d_in[8];
    const float* dz = (const float*)d_in[9];
    float* out = (float*)d_out;

    static __half *xh_p, *wg_p, *wu_p, *wd_p, *t1_p, *h_p;
    static bool init_done = false;
    if (!init_done) {
        cudaGetSymbolAddress((void**)&xh_p, g_xh);
        cudaGetSymbolAddress((void**)&wg_p, g_Wg);
        cudaGetSymbolAddress((void**)&wu_p, g_Wu);
        cudaGetSymbolAddress((void**)&wd_p, g_Wd);
        cudaGetSymbolAddress((void**)&t1_p, g_t1);
        cudaGetSymbolAddress((void**)&h_p,  g_h);
        cudaFuncSetAttribute(gemm_hmma<0>, cudaFuncAttributeMaxDynamicSharedMemorySize, GEMM_SMEM);
        cudaFuncSetAttribute(gemm_hmma<1>, cudaFuncAttributeMaxDynamicSharedMemorySize, GEMM_SMEM);
        cudaFuncSetAttribute(gemm_hmma<2>, cudaFuncAttributeMaxDynamicSharedMemorySize, GEMM_SMEM);
        init_done = true;
    }

    // Prepass: x -> fp16, weights -> dequantized fp16 K-major (transposed)
    cvt_x_kernel<<<(M_DIM * D_DIM) / (256 * 4), 256>>>(x);
    dequant_t_kernel<<<dim3(I_DIM / 32, D_DIM / 32), dim3(32, 8)>>>(gq, gs, gz, wg_p, D_DIM, I_DIM);
    dequant_t_kernel<<<dim3(I_DIM / 32, D_DIM / 32), dim3(32, 8)>>>(uq, us, uz, wu_p, D_DIM, I_DIM);
    dequant_t_kernel<<<dim3(D_DIM / 32, I_DIM / 32), dim3(32, 8)>>>(dq, ds, dz, wd_p, I_DIM, D_DIM);

    // gate = x @ Wg  -> g_t1 (fp16, pre-activation)
    gemm_hmma<0><<<dim3(M_DIM / 128, I_DIM / 128), 256, GEMM_SMEM>>>(
        xh_p, wg_p, (void*)t1_p, nullptr, D_DIM, I_DIM);
    // up GEMM with fused silu:  h = silu(gate) * (x @ Wu)  -> g_h (fp16)
    gemm_hmma<1><<<dim3(M_DIM / 128, I_DIM / 128), 256, GEMM_SMEM>>>(
        xh_p, wu_p, (void*)h_p, t1_p, D_DIM, I_DIM);
    // out = h @ Wd -> fp32
    gemm_hmma<2><<<dim3(M_DIM / 128, D_DIM / 128), 256, GEMM_SMEM>>>(
        h_p, wd_p, (void*)out, nullptr, I_DIM, D_DIM);
}

// round 5
// speedup vs baseline: 1.1461x; 1.1461x over previous
#include <cuda_runtime.h>
#include <cuda_fp16.h>
#include <cstdint>

// ---------------- Problem dims (fixed by the dataset) ----------------
#define D_DIM 4096
#define I_DIM 11008
#define M_DIM 8192          // 4 * 2048 tokens

// ---------------- Scratch (device globals: allocation-free) ----------
__device__ __half g_xh[(size_t)M_DIM * D_DIM];     //  64 MB  x in fp16 [M, D]
__device__ __half g_Wg[(size_t)I_DIM * D_DIM];     //  90 MB  gate W^T [I, D] (K-major)
__device__ __half g_Wu[(size_t)I_DIM * D_DIM];     //  90 MB  up   W^T [I, D]
__device__ __half g_Wd[(size_t)D_DIM * I_DIM];     //  90 MB  down W^T [D, I]
__device__ __half g_t1[(size_t)M_DIM * I_DIM];     // 176 MB  gate pre-activation fp16
__device__ __half g_h [(size_t)M_DIM * I_DIM];     // 176 MB  h = silu(gate)*up [M, I]

// ---------------- helpers ----------------------------------------
__device__ __forceinline__ uint32_t smem_u32(const void* p) {
    uint32_t a;
    asm("{ .reg .u64 t; cvta.to.shared.u64 t, %1; cvt.u32.u64 %0, t; }" : "=r"(a) : "l"(p));
    return a;
}
__device__ __forceinline__ void cp16(uint32_t s, const void* g) {
    asm volatile("cp.async.cg.shared.global [%0], [%1], 16;" :: "r"(s), "l"(g));
}
#define CP_COMMIT() asm volatile("cp.async.commit_group;" ::: "memory")
#define CP_WAIT1()  asm volatile("cp.async.wait_group 1;" ::: "memory")

#define LDSM_X4(r, addr) \
    asm volatile("ldmatrix.sync.aligned.m8n8.x4.shared.b16 {%0,%1,%2,%3}, [%4];" \
        : "=r"((r)[0]), "=r"((r)[1]), "=r"((r)[2]), "=r"((r)[3]) : "r"(addr))

__device__ __forceinline__ void mma16816(float* c, const uint32_t* a,
                                         uint32_t b0, uint32_t b1) {
    asm volatile(
        "mma.sync.aligned.m16n8k16.row.col.f32.f16.f16.f32 "
        "{%0,%1,%2,%3}, {%4,%5,%6,%7}, {%8,%9}, {%0,%1,%2,%3};"
        : "+f"(c[0]), "+f"(c[1]), "+f"(c[2]), "+f"(c[3])
        : "r"(a[0]), "r"(a[1]), "r"(a[2]), "r"(a[3]), "r"(b0), "r"(b1));
}

// ---------------- Prepass kernels -------------------------------------
__global__ void cvt_x_kernel(const float* __restrict__ x) {
    size_t i = ((size_t)blockIdx.x * blockDim.x + threadIdx.x) * 4;
    float4 v = *(const float4*)(x + i);
    __half2* o = (__half2*)(g_xh + i);
    o[0] = __floats2half2_rn(v.x, v.y);
    o[1] = __floats2half2_rn(v.z, v.w);
}

// q:[K,N] int32 (0..15), s/z:[K/128,N].  Out: Wt[N,K] fp16, Wt[n,k] = (q[k,n]-8)*s+z
__global__ void dequant_t_kernel(const int* __restrict__ q, const float* __restrict__ s,
                                 const float* __restrict__ z, __half* __restrict__ Wt,
                                 int K, int N) {
    __shared__ __half tile[32][33];
    int n0 = blockIdx.x * 32, k0 = blockIdx.y * 32;
    int tx = threadIdx.x, ty = threadIdx.y;          // block (32, 8)
    int n = n0 + tx;
    int grp = k0 >> 7;                               // whole 32-row tile in one group
    float sv = s[(size_t)grp * N + n];
    float zv = z[(size_t)grp * N + n];
#pragma unroll
    for (int i = 0; i < 4; i++) {
        int k = k0 + ty + i * 8;
        int qv = q[(size_t)k * N + n];
        tile[ty + i * 8][tx] = __float2half((float)(qv - 8) * sv + zv);
    }
    __syncthreads();
#pragma unroll
    for (int i = 0; i < 4; i++) {
        int nn = n0 + ty + i * 8;
        Wt[(size_t)nn * K + k0 + tx] = tile[tx][ty + i * 8];
    }
}

// ---------------- HMMA GEMM ----------------------------------------
// C[M,N] = A[M,K] @ B[N,K]^T.  A,B fp16 K-major.
// CTA tile 256x128, BK=32, 256 threads = 8 warps (4 along M x 2 along N),
// warp tile 64x64.  3-stage cp.async pipeline, 80B SMEM row pitch.
// MODE 0: store fp16 raw (gate).  MODE 1: h = silu(aux)*acc, fp16 (up+silu).
// MODE 2: store fp32 (down output).
static constexpr int A_BYTES   = 256 * 80;           // 20480
static constexpr int STAGE_B   = 384 * 80;           // 30720 (A 256 rows + B 128 rows)
static constexpr int GEMM_SMEM = 3 * STAGE_B;        // 92160

template <int MODE>
__global__ void __launch_bounds__(256, 1)
gemm_hmma(const __half* __restrict__ Ag, const __half* __restrict__ Bg,
          void* __restrict__ Cg, const __half* __restrict__ aux,
          int K, int N) {
    extern __shared__ char smem[];
    uint32_t sb = smem_u32(smem);
    int tid = threadIdx.x;
    int lane = tid & 31, warp = tid >> 5;
    int wm = (warp & 3) * 64;        // warp M offset in tile (0..192)
    int wn = (warp >> 2) * 64;       // warp N offset in tile (0 or 64)
    int m0 = blockIdx.x * 256;
    int n0 = blockIdx.y * 128;

    const __half* gA = Ag + (size_t)m0 * K;
    const __half* gB = Bg + (size_t)n0 * K;

    auto load_stage = [&](int s, int k0) {
        uint32_t sa = sb + (uint32_t)s * STAGE_B;
#pragma unroll
        for (int i = 0; i < 4; i++) {                 // A: 256 rows x 64B
            int id = tid + i * 256;
            int r = id >> 2, c = id & 3;
            cp16(sa + r * 80 + c * 16, gA + (size_t)r * K + k0 + c * 8);
        }
#pragma unroll
        for (int i = 0; i < 2; i++) {                 // B: 128 rows x 64B
            int id = tid + i * 256;
            int r = id >> 2, c = id & 3;
            cp16(sa + A_BYTES + r * 80 + c * 16, gB + (size_t)r * K + k0 + c * 8);
        }
    };

    float acc[4][8][4];
#pragma unroll
    for (int i = 0; i < 4; i++)
#pragma unroll
        for (int j = 0; j < 8; j++)
#pragma unroll
            for (int l = 0; l < 4; l++) acc[i][j][l] = 0.0f;

    load_stage(0, 0);  CP_COMMIT();
    load_stage(1, 32); CP_COMMIT();

    int nk = K / 32;
#pragma unroll 1
    for (int k = 0; k < nk; k++) {
        CP_WAIT1();
        __syncthreads();
        if (k + 2 < nk) load_stage((k + 2) % 3, (k + 2) * 32);
        CP_COMMIT();

        uint32_t sa = sb + (uint32_t)(k % 3) * STAGE_B;
        uint32_t sB = sa + A_BYTES;
#pragma unroll
        for (int ks = 0; ks < 2; ks++) {
            uint32_t a[4][4], b[4][4];
#pragma unroll
            for (int mi = 0; mi < 4; mi++) {
                uint32_t addr = sa + (uint32_t)((wm + mi * 16 + (lane & 15)) * 80
                              + (ks * 16 + (lane >> 4) * 8) * 2);
                LDSM_X4(a[mi], addr);
            }
#pragma unroll
            for (int bi = 0; bi < 4; bi++) {
                int n = wn + bi * 16 + (lane & 7) + ((lane >> 4) & 1) * 8;
                int kk = ks * 16 + ((lane >> 3) & 1) * 8;
                uint32_t addr = sB + (uint32_t)(n * 80 + kk * 2);
                LDSM_X4(b[bi], addr);
            }
#pragma unroll
            for (int mi = 0; mi < 4; mi++)
#pragma unroll
                for (int bi = 0; bi < 4; bi++) {
                    mma16816(acc[mi][2 * bi],     a[mi], b[bi][0], b[bi][1]);
                    mma16816(acc[mi][2 * bi + 1], a[mi], b[bi][2], b[bi][3]);
                }
        }
    }

    // ---- epilogue ----
    int r0 = m0 + wm + (lane >> 2);
    int c0 = n0 + wn + (lane & 3) * 2;
#pragma unroll
    for (int mi = 0; mi < 4; mi++) {
#pragma unroll
        for (int hi = 0; hi < 2; hi++) {
            int row = r0 + mi * 16 + hi * 8;
#pragma unroll
            for (int ni = 0; ni < 8; ni++) {
                int col = c0 + ni * 8;
                float v0 = acc[mi][ni][2 * hi], v1 = acc[mi][ni][2 * hi + 1];
                if (MODE == 0) {
                    *(__half2*)((__half*)Cg + (size_t)row * N + col) =
                        __floats2half2_rn(v0, v1);
                } else if (MODE == 1) {
                    __half2 gh = *(const __half2*)(aux + (size_t)row * N + col);
                    float g0 = __half2float(gh.x), g1 = __half2float(gh.y);
                    float h0 = g0 / (1.0f + __expf(-g0)) * v0;
                    float h1 = g1 / (1.0f + __expf(-g1)) * v1;
                    *(__half2*)((__half*)Cg + (size_t)row * N + col) =
                        __floats2half2_rn(h0, h1);
                } else {
                    *(float2*)((float*)Cg + (size_t)row * N + col) =
                        make_float2(v0, v1);
                }
            }
        }
    }
}

// ---------------- Launch ----------------------------------------------
extern "C" void kernel_launch(void* const* d_in, const int* in_sizes, int n_in,
                              void* d_out, int out_size) {
    (void)in_sizes; (void)n_in; (void)out_size;
    const float* x  = (const float*)d_in[0];
    const int*   gq = (const int*)  d_in[1];
    const float* gs = (const float*)d_in[2];
    const float* gz = (const float*)d_in[3];
    const int*   uq = (const int*)  d_in[4];
    const float* us = (const float*)d_in[5];
    const float* uz = (const float*)d_in[6];
    const int*   dq = (const int*)  d_in[7];
    const float* ds = (const float*)d_in[8];
    const float* dz = (const float*)d_in[9];
    float* out = (float*)d_out;

    static __half *xh_p, *wg_p, *wu_p, *wd_p, *t1_p, *h_p;
    static bool init_done = false;
    if (!init_done) {
        cudaGetSymbolAddress((void**)&xh_p, g_xh);
        cudaGetSymbolAddress((void**)&wg_p, g_Wg);
        cudaGetSymbolAddress((void**)&wu_p, g_Wu);
        cudaGetSymbolAddress((void**)&wd_p, g_Wd);
        cudaGetSymbolAddress((void**)&t1_p, g_t1);
        cudaGetSymbolAddress((void**)&h_p,  g_h);
        cudaFuncSetAttribute(gemm_hmma<0>, cudaFuncAttributeMaxDynamicSharedMemorySize, GEMM_SMEM);
        cudaFuncSetAttribute(gemm_hmma<1>, cudaFuncAttributeMaxDynamicSharedMemorySize, GEMM_SMEM);
        cudaFuncSetAttribute(gemm_hmma<2>, cudaFuncAttributeMaxDynamicSharedMemorySize, GEMM_SMEM);
        init_done = true;
    }

    // Prepass: x -> fp16, weights -> dequantized fp16 K-major (transposed)
    cvt_x_kernel<<<(M_DIM * D_DIM) / (256 * 4), 256>>>(x);
    dequant_t_kernel<<<dim3(I_DIM / 32, D_DIM / 32), dim3(32, 8)>>>(gq, gs, gz, wg_p, D_DIM, I_DIM);
    dequant_t_kernel<<<dim3(I_DIM / 32, D_DIM / 32), dim3(32, 8)>>>(uq, us, uz, wu_p, D_DIM, I_DIM);
    dequant_t_kernel<<<dim3(D_DIM / 32, I_DIM / 32), dim3(32, 8)>>>(dq, ds, dz, wd_p, I_DIM, D_DIM);

    // gate = x @ Wg  -> g_t1 (fp16, pre-activation)
    gemm_hmma<0><<<dim3(M_DIM / 256, I_DIM / 128), 256, GEMM_SMEM>>>(
        xh_p, wg_p, (void*)t1_p, nullptr, D_DIM, I_DIM);
    // up GEMM with fused silu:  h = silu(gate) * (x @ Wu)  -> g_h (fp16)
    gemm_hmma<1><<<dim3(M_DIM / 256, I_DIM / 128), 256, GEMM_SMEM>>>(
        xh_p, wu_p, (void*)h_p, t1_p, D_DIM, I_DIM);
    // out = h @ Wd -> fp32
    gemm_hmma<2><<<dim3(M_DIM / 256, D_DIM / 128), 256, GEMM_SMEM>>>(
        h_p, wd_p, (void*)out, nullptr, I_DIM, D_DIM);
}

// round 6
// speedup vs baseline: 1.3108x; 1.1437x over previous
#include <cuda_runtime.h>
#include <cuda_fp16.h>
#include <cstdint>

// ---------------- Problem dims (fixed by the dataset) ----------------
#define D_DIM 4096
#define I_DIM 11008
#define M_DIM 8192          // 4 * 2048 tokens

// ---------------- Scratch (device globals: allocation-free) ----------
__device__ __half g_xh[(size_t)M_DIM * D_DIM];     //  64 MB  x in fp16 [M, D]
__device__ __half g_Wg[(size_t)I_DIM * D_DIM];     //  90 MB  gate W^T [I, D] (K-major)
__device__ __half g_Wu[(size_t)I_DIM * D_DIM];     //  90 MB  up   W^T [I, D]
__device__ __half g_Wd[(size_t)D_DIM * I_DIM];     //  90 MB  down W^T [D, I]
__device__ __half g_t1[(size_t)M_DIM * I_DIM];     // 176 MB  gate pre-activation fp16
__device__ __half g_h [(size_t)M_DIM * I_DIM];     // 176 MB  h = silu(gate)*up [M, I]

// ---------------- helpers ----------------------------------------
__device__ __forceinline__ uint32_t smem_u32(const void* p) {
    uint32_t a;
    asm("{ .reg .u64 t; cvta.to.shared.u64 t, %1; cvt.u32.u64 %0, t; }" : "=r"(a) : "l"(p));
    return a;
}
__device__ __forceinline__ void cp16(uint32_t s, const void* g) {
    asm volatile("cp.async.cg.shared.global [%0], [%1], 16;" :: "r"(s), "l"(g));
}
#define CP_COMMIT() asm volatile("cp.async.commit_group;" ::: "memory")
#define CP_WAIT1()  asm volatile("cp.async.wait_group 1;" ::: "memory")

#define LDSM_X4(r, addr) \
    asm volatile("ldmatrix.sync.aligned.m8n8.x4.shared.b16 {%0,%1,%2,%3}, [%4];" \
        : "=r"((r)[0]), "=r"((r)[1]), "=r"((r)[2]), "=r"((r)[3]) : "r"(addr))

__device__ __forceinline__ void mma16816(float* c, const uint32_t* a,
                                         uint32_t b0, uint32_t b1) {
    asm volatile(
        "mma.sync.aligned.m16n8k16.row.col.f32.f16.f16.f32 "
        "{%0,%1,%2,%3}, {%4,%5,%6,%7}, {%8,%9}, {%0,%1,%2,%3};"
        : "+f"(c[0]), "+f"(c[1]), "+f"(c[2]), "+f"(c[3])
        : "r"(a[0]), "r"(a[1]), "r"(a[2]), "r"(a[3]), "r"(b0), "r"(b1));
}

// ---------------- Prepass kernels -------------------------------------
__global__ void cvt_x_kernel(const float* __restrict__ x) {
    size_t i = ((size_t)blockIdx.x * blockDim.x + threadIdx.x) * 4;
    float4 v = *(const float4*)(x + i);
    __half2* o = (__half2*)(g_xh + i);
    o[0] = __floats2half2_rn(v.x, v.y);
    o[1] = __floats2half2_rn(v.z, v.w);
}

// q:[K,N] int32 (0..15), s/z:[K/128,N].  Out: Wt[N,K] fp16, Wt[n,k] = (q[k,n]-8)*s+z
__global__ void dequant_t_kernel(const int* __restrict__ q, const float* __restrict__ s,
                                 const float* __restrict__ z, __half* __restrict__ Wt,
                                 int K, int N) {
    __shared__ __half tile[32][33];
    int n0 = blockIdx.x * 32, k0 = blockIdx.y * 32;
    int tx = threadIdx.x, ty = threadIdx.y;          // block (32, 8)
    int n = n0 + tx;
    int grp = k0 >> 7;                               // whole 32-row tile in one group
    float sv = s[(size_t)grp * N + n];
    float zv = z[(size_t)grp * N + n];
#pragma unroll
    for (int i = 0; i < 4; i++) {
        int k = k0 + ty + i * 8;
        int qv = q[(size_t)k * N + n];
        tile[ty + i * 8][tx] = __float2half((float)(qv - 8) * sv + zv);
    }
    __syncthreads();
#pragma unroll
    for (int i = 0; i < 4; i++) {
        int nn = n0 + ty + i * 8;
        Wt[(size_t)nn * K + k0 + tx] = tile[tx][ty + i * 8];
    }
}

// ---------------- HMMA GEMM ----------------------------------------
// C[M,N] = A[M,K] @ B[N,K]^T.  A,B fp16 K-major.
// CTA tile 256x128, BK=64, 256 threads = 8 warps (4 along M x 2 along N),
// warp tile 64x64.  3-stage cp.async pipeline, 144B SMEM row pitch
// (128B data + 16B pad -> bank stride 4 mod 32, ldmatrix conflict-free).
// MODE 0: store fp16 raw (gate).  MODE 1: h = silu(aux)*acc, fp16 (up+silu).
// MODE 2: store fp32 (down output).
static constexpr int ROW_PITCH = 144;
static constexpr int A_BYTES   = 256 * ROW_PITCH;        // 36864
static constexpr int STAGE_B   = 384 * ROW_PITCH;        // 55296
static constexpr int GEMM_SMEM = 3 * STAGE_B;            // 165888

template <int MODE>
__global__ void __launch_bounds__(256, 1)
gemm_hmma(const __half* __restrict__ Ag, const __half* __restrict__ Bg,
          void* __restrict__ Cg, const __half* __restrict__ aux,
          int K, int N) {
    extern __shared__ char smem[];
    uint32_t sb = smem_u32(smem);
    int tid = threadIdx.x;
    int lane = tid & 31, warp = tid >> 5;
    int wm = (warp & 3) * 64;        // warp M offset in tile (0..192)
    int wn = (warp >> 2) * 64;       // warp N offset in tile (0 or 64)
    int m0 = blockIdx.x * 256;
    int n0 = blockIdx.y * 128;

    const __half* gA = Ag + (size_t)m0 * K;
    const __half* gB = Bg + (size_t)n0 * K;

    auto load_stage = [&](int s, int k0) {
        uint32_t sa = sb + (uint32_t)s * STAGE_B;
#pragma unroll
        for (int i = 0; i < 8; i++) {                 // A: 256 rows x 128B
            int id = tid + i * 256;
            int r = id >> 3, c = id & 7;
            cp16(sa + r * ROW_PITCH + c * 16, gA + (size_t)r * K + k0 + c * 8);
        }
#pragma unroll
        for (int i = 0; i < 4; i++) {                 // B: 128 rows x 128B
            int id = tid + i * 256;
            int r = id >> 3, c = id & 7;
            cp16(sa + A_BYTES + r * ROW_PITCH + c * 16, gB + (size_t)r * K + k0 + c * 8);
        }
    };

    float acc[4][8][4];
#pragma unroll
    for (int i = 0; i < 4; i++)
#pragma unroll
        for (int j = 0; j < 8; j++)
#pragma unroll
            for (int l = 0; l < 4; l++) acc[i][j][l] = 0.0f;

    load_stage(0, 0);  CP_COMMIT();
    load_stage(1, 64); CP_COMMIT();

    int nk = K / 64;
#pragma unroll 1
    for (int k = 0; k < nk; k++) {
        CP_WAIT1();
        __syncthreads();
        if (k + 2 < nk) load_stage((k + 2) % 3, (k + 2) * 64);
        CP_COMMIT();

        uint32_t sa = sb + (uint32_t)(k % 3) * STAGE_B;
        uint32_t sB = sa + A_BYTES;
#pragma unroll
        for (int ks = 0; ks < 4; ks++) {
            uint32_t a[4][4], b[4][4];
#pragma unroll
            for (int mi = 0; mi < 4; mi++) {
                uint32_t addr = sa + (uint32_t)((wm + mi * 16 + (lane & 15)) * ROW_PITCH
                              + (ks * 16 + (lane >> 4) * 8) * 2);
                LDSM_X4(a[mi], addr);
            }
#pragma unroll
            for (int bi = 0; bi < 4; bi++) {
                int n = wn + bi * 16 + (lane & 7) + ((lane >> 4) & 1) * 8;
                int kk = ks * 16 + ((lane >> 3) & 1) * 8;
                uint32_t addr = sB + (uint32_t)(n * ROW_PITCH + kk * 2);
                LDSM_X4(b[bi], addr);
            }
#pragma unroll
            for (int mi = 0; mi < 4; mi++)
#pragma unroll
                for (int bi = 0; bi < 4; bi++) {
                    mma16816(acc[mi][2 * bi],     a[mi], b[bi][0], b[bi][1]);
                    mma16816(acc[mi][2 * bi + 1], a[mi], b[bi][2], b[bi][3]);
                }
        }
    }

    // ---- epilogue ----
    int r0 = m0 + wm + (lane >> 2);
    int c0 = n0 + wn + (lane & 3) * 2;
#pragma unroll
    for (int mi = 0; mi < 4; mi++) {
#pragma unroll
        for (int hi = 0; hi < 2; hi++) {
            int row = r0 + mi * 16 + hi * 8;
#pragma unroll
            for (int ni = 0; ni < 8; ni++) {
                int col = c0 + ni * 8;
                float v0 = acc[mi][ni][2 * hi], v1 = acc[mi][ni][2 * hi + 1];
                if (MODE == 0) {
                    *(__half2*)((__half*)Cg + (size_t)row * N + col) =
                        __floats2half2_rn(v0, v1);
                } else if (MODE == 1) {
                    __half2 gh = *(const __half2*)(aux + (size_t)row * N + col);
                    float g0 = __half2float(gh.x), g1 = __half2float(gh.y);
                    float h0 = g0 / (1.0f + __expf(-g0)) * v0;
                    float h1 = g1 / (1.0f + __expf(-g1)) * v1;
                    *(__half2*)((__half*)Cg + (size_t)row * N + col) =
                        __floats2half2_rn(h0, h1);
                } else {
                    *(float2*)((float*)Cg + (size_t)row * N + col) =
                        make_float2(v0, v1);
                }
            }
        }
    }
}

// ---------------- Launch ----------------------------------------------
extern "C" void kernel_launch(void* const* d_in, const int* in_sizes, int n_in,
                              void* d_out, int out_size) {
    (void)in_sizes; (void)n_in; (void)out_size;
    const float* x  = (const float*)d_in[0];
    const int*   gq = (const int*)  d_in[1];
    const float* gs = (const float*)d_in[2];
    const float* gz = (const float*)d_in[3];
    const int*   uq = (const int*)  d_in[4];
    const float* us = (const float*)d_in[5];
    const float* uz = (const float*)d_in[6];
    const int*   dq = (const int*)  d_in[7];
    const float* ds = (const float*)d_in[8];
    const float* dz = (const float*)d_in[9];
    float* out = (float*)d_out;

    static __half *xh_p, *wg_p, *wu_p, *wd_p, *t1_p, *h_p;
    static bool init_done = false;
    if (!init_done) {
        cudaGetSymbolAddress((void**)&xh_p, g_xh);
        cudaGetSymbolAddress((void**)&wg_p, g_Wg);
        cudaGetSymbolAddress((void**)&wu_p, g_Wu);
        cudaGetSymbolAddress((void**)&wd_p, g_Wd);
        cudaGetSymbolAddress((void**)&t1_p, g_t1);
        cudaGetSymbolAddress((void**)&h_p,  g_h);
        cudaFuncSetAttribute(gemm_hmma<0>, cudaFuncAttributeMaxDynamicSharedMemorySize, GEMM_SMEM);
        cudaFuncSetAttribute(gemm_hmma<1>, cudaFuncAttributeMaxDynamicSharedMemorySize, GEMM_SMEM);
        cudaFuncSetAttribute(gemm_hmma<2>, cudaFuncAttributeMaxDynamicSharedMemorySize, GEMM_SMEM);
        init_done = true;
    }

    // Prepass: x -> fp16, weights -> dequantized fp16 K-major (transposed)
    cvt_x_kernel<<<(M_DIM * D_DIM) / (256 * 4), 256>>>(x);
    dequant_t_kernel<<<dim3(I_DIM / 32, D_DIM / 32), dim3(32, 8)>>>(gq, gs, gz, wg_p, D_DIM, I_DIM);
    dequant_t_kernel<<<dim3(I_DIM / 32, D_DIM / 32), dim3(32, 8)>>>(uq, us, uz, wu_p, D_DIM, I_DIM);
    dequant_t_kernel<<<dim3(D_DIM / 32, I_DIM / 32), dim3(32, 8)>>>(dq, ds, dz, wd_p, I_DIM, D_DIM);

    // gate = x @ Wg  -> g_t1 (fp16, pre-activation)
    gemm_hmma<0><<<dim3(M_DIM / 256, I_DIM / 128), 256, GEMM_SMEM>>>(
        xh_p, wg_p, (void*)t1_p, nullptr, D_DIM, I_DIM);
    // up GEMM with fused silu:  h = silu(gate) * (x @ Wu)  -> g_h (fp16)
    gemm_hmma<1><<<dim3(M_DIM / 256, I_DIM / 128), 256, GEMM_SMEM>>>(
        xh_p, wu_p, (void*)h_p, t1_p, D_DIM, I_DIM);
    // out = h @ Wd -> fp32
    gemm_hmma<2><<<dim3(M_DIM / 256, D_DIM / 128), 256, GEMM_SMEM>>>(
        h_p, wd_p, (void*)out, nullptr, I_DIM, D_DIM);
}

// round 8
// speedup vs baseline: 1.3642x; 1.0408x over previous
#include <cuda_runtime.h>
#include <cuda_fp16.h>
#include <cstdint>

// ---------------- Problem dims (fixed by the dataset) ----------------
#define D_DIM 4096
#define I_DIM 11008
#define M_DIM 8192          // 4 * 2048 tokens

// ---------------- Scratch (device globals: allocation-free) ----------
__device__ __half g_xh[(size_t)M_DIM * D_DIM];     //  64 MB  x in fp16 [M, D]
__device__ __half g_Wg[(size_t)I_DIM * D_DIM];     //  90 MB  gate W^T [I, D] (K-major)
__device__ __half g_Wu[(size_t)I_DIM * D_DIM];     //  90 MB  up   W^T [I, D]
__device__ __half g_Wd[(size_t)D_DIM * I_DIM];     //  90 MB  down W^T [D, I]
__device__ __half g_t1[(size_t)M_DIM * I_DIM];     // 176 MB  gate pre-activation fp16
__device__ __half g_h [(size_t)M_DIM * I_DIM];     // 176 MB  h = silu(gate)*up [M, I]

// ---------------- helpers ----------------------------------------
__device__ __forceinline__ uint32_t smem_u32(const void* p) {
    uint32_t a;
    asm("{ .reg .u64 t; cvta.to.shared.u64 t, %1; cvt.u32.u64 %0, t; }" : "=r"(a) : "l"(p));
    return a;
}
__device__ __forceinline__ void cp16(uint32_t s, const void* g) {
    asm volatile("cp.async.cg.shared.global [%0], [%1], 16;" :: "r"(s), "l"(g));
}
#define CP_COMMIT() asm volatile("cp.async.commit_group;" ::: "memory")
#define CP_WAIT0()  asm volatile("cp.async.wait_group 0;" ::: "memory")

#define LDSM_X4(r, addr) \
    asm volatile("ldmatrix.sync.aligned.m8n8.x4.shared.b16 {%0,%1,%2,%3}, [%4];" \
        : "=r"((r)[0]), "=r"((r)[1]), "=r"((r)[2]), "=r"((r)[3]) : "r"(addr))

__device__ __forceinline__ void mma16816(float* c, const uint32_t* a,
                                         uint32_t b0, uint32_t b1) {
    asm volatile(
        "mma.sync.aligned.m16n8k16.row.col.f32.f16.f16.f32 "
        "{%0,%1,%2,%3}, {%4,%5,%6,%7}, {%8,%9}, {%0,%1,%2,%3};"
        : "+f"(c[0]), "+f"(c[1]), "+f"(c[2]), "+f"(c[3])
        : "r"(a[0]), "r"(a[1]), "r"(a[2]), "r"(a[3]), "r"(b0), "r"(b1));
}

// ---------------- Prepass kernels -------------------------------------
__global__ void cvt_x_kernel(const float* __restrict__ x) {
    size_t i = ((size_t)blockIdx.x * blockDim.x + threadIdx.x) * 4;
    float4 v = *(const float4*)(x + i);
    __half2* o = (__half2*)(g_xh + i);
    o[0] = __floats2half2_rn(v.x, v.y);
    o[1] = __floats2half2_rn(v.z, v.w);
}

// q:[K,N] int32 (0..15), s/z:[K/128,N].  Out: Wt[N,K] fp16, Wt[n,k] = (q[k,n]-8)*s+z
__global__ void dequant_t_kernel(const int* __restrict__ q, const float* __restrict__ s,
                                 const float* __restrict__ z, __half* __restrict__ Wt,
                                 int K, int N) {
    __shared__ __half tile[32][33];
    int n0 = blockIdx.x * 32, k0 = blockIdx.y * 32;
    int tx = threadIdx.x, ty = threadIdx.y;          // block (32, 8)
    int n = n0 + tx;
    int grp = k0 >> 7;                               // whole 32-row tile in one group
    float sv = s[(size_t)grp * N + n];
    float zv = z[(size_t)grp * N + n];
#pragma unroll
    for (int i = 0; i < 4; i++) {
        int k = k0 + ty + i * 8;
        int qv = q[(size_t)k * N + n];
        tile[ty + i * 8][tx] = __float2half((float)(qv - 8) * sv + zv);
    }
    __syncthreads();
#pragma unroll
    for (int i = 0; i < 4; i++) {
        int nn = n0 + ty + i * 8;
        Wt[(size_t)nn * K + k0 + tx] = tile[tx][ty + i * 8];
    }
}

// ---------------- HMMA GEMM ----------------------------------------
// C[M,N] = A[M,K] @ B[N,K]^T.  A,B fp16 K-major.
// CTA tile 256x128, BK=128, 256 threads = 8 warps (4 along M x 2 along N),
// warp tile 64x64.  2-stage cp.async double buffer, 272B SMEM row pitch
// (256B data + 16B pad -> bank stride 4 mod 32, ldmatrix conflict-free).
// MODE 0: store fp16 raw (gate).  MODE 1: h = silu(aux)*acc, fp16 (up+silu).
// MODE 2: store fp32 (down output).
static constexpr int ROW_PITCH = 272;
static constexpr int A_BYTES   = 256 * ROW_PITCH;        // 69632
static constexpr int STAGE_B   = 384 * ROW_PITCH;        // 104448
static constexpr int GEMM_SMEM = 2 * STAGE_B;            // 208896

template <int MODE>
__global__ void __launch_bounds__(256, 1)
gemm_hmma(const __half* __restrict__ Ag, const __half* __restrict__ Bg,
          void* __restrict__ Cg, const __half* __restrict__ aux,
          int K, int N) {
    extern __shared__ char smem[];
    uint32_t sb = smem_u32(smem);
    int tid = threadIdx.x;
    int lane = tid & 31, warp = tid >> 5;
    int wm = (warp & 3) * 64;        // warp M offset in tile (0..192)
    int wn = (warp >> 2) * 64;       // warp N offset in tile (0 or 64)
    int m0 = blockIdx.x * 256;
    int n0 = blockIdx.y * 128;

    const __half* gA = Ag + (size_t)m0 * K;
    const __half* gB = Bg + (size_t)n0 * K;

    auto load_stage = [&](int s, int k0) {
        uint32_t sa = sb + (uint32_t)s * STAGE_B;
#pragma unroll
        for (int i = 0; i < 16; i++) {                // A: 256 rows x 256B
            int id = tid + i * 256;
            int r = id >> 4, c = id & 15;
            cp16(sa + r * ROW_PITCH + c * 16, gA + (size_t)r * K + k0 + c * 8);
        }
#pragma unroll
        for (int i = 0; i < 8; i++) {                 // B: 128 rows x 256B
            int id = tid + i * 256;
            int r = id >> 4, c = id & 15;
            cp16(sa + A_BYTES + r * ROW_PITCH + c * 16, gB + (size_t)r * K + k0 + c * 8);
        }
    };

    float acc[4][8][4];
#pragma unroll
    for (int i = 0; i < 4; i++)
#pragma unroll
        for (int j = 0; j < 8; j++)
#pragma unroll
            for (int l = 0; l < 4; l++) acc[i][j][l] = 0.0f;

    load_stage(0, 0);  CP_COMMIT();

    int nk = K / 128;
#pragma unroll 1
    for (int k = 0; k < nk; k++) {
        CP_WAIT0();                                   // stage k resident
        __syncthreads();                              // everyone done with other buffer
        if (k + 1 < nk) {                             // prefetch k+1 into other buffer
            load_stage((k + 1) & 1, (k + 1) * 128);
            CP_COMMIT();
        }

        uint32_t sa = sb + (uint32_t)(k & 1) * STAGE_B;
        uint32_t sB = sa + A_BYTES;
#pragma unroll
        for (int ks = 0; ks < 8; ks++) {
            uint32_t a[4][4], b[4][4];
#pragma unroll
            for (int mi = 0; mi < 4; mi++) {
                uint32_t addr = sa + (uint32_t)((wm + mi * 16 + (lane & 15)) * ROW_PITCH
                              + (ks * 16 + (lane >> 4) * 8) * 2);
                LDSM_X4(a[mi], addr);
            }
#pragma unroll
            for (int bi = 0; bi < 4; bi++) {
                int n = wn + bi * 16 + (lane & 7) + ((lane >> 4) & 1) * 8;
                int kk = ks * 16 + ((lane >> 3) & 1) * 8;
                uint32_t addr = sB + (uint32_t)(n * ROW_PITCH + kk * 2);
                LDSM_X4(b[bi], addr);
            }
#pragma unroll
            for (int mi = 0; mi < 4; mi++)
#pragma unroll
                for (int bi = 0; bi < 4; bi++) {
                    mma16816(acc[mi][2 * bi],     a[mi], b[bi][0], b[bi][1]);
                    mma16816(acc[mi][2 * bi + 1], a[mi], b[bi][2], b[bi][3]);
                }
        }
        __syncthreads();                              // done reading stage k
    }

    // ---- epilogue ----
    int r0 = m0 + wm + (lane >> 2);
    int c0 = n0 + wn + (lane & 3) * 2;
#pragma unroll
    for (int mi = 0; mi < 4; mi++) {
#pragma unroll
        for (int hi = 0; hi < 2; hi++) {
            int row = r0 + mi * 16 + hi * 8;
#pragma unroll
            for (int ni = 0; ni < 8; ni++) {
                int col = c0 + ni * 8;
                float v0 = acc[mi][ni][2 * hi], v1 = acc[mi][ni][2 * hi + 1];
                if (MODE == 0) {
                    *(__half2*)((__half*)Cg + (size_t)row * N + col) =
                        __floats2half2_rn(v0, v1);
                } else if (MODE == 1) {
                    __half2 gh = *(const __half2*)(aux + (size_t)row * N + col);
                    float g0 = __half2float(gh.x), g1 = __half2float(gh.y);
                    float h0 = g0 / (1.0f + __expf(-g0)) * v0;
                    float h1 = g1 / (1.0f + __expf(-g1)) * v1;
                    *(__half2*)((__half*)Cg + (size_t)row * N + col) =
                        __floats2half2_rn(h0, h1);
                } else {
                    *(float2*)((float*)Cg + (size_t)row * N + col) =
                        make_float2(v0, v1);
                }
            }
        }
    }
}

// ---------------- Launch ----------------------------------------------
extern "C" void kernel_launch(void* const* d_in, const int* in_sizes, int n_in,
                              void* d_out, int out_size) {
    (void)in_sizes; (void)n_in; (void)out_size;
    const float* x  = (const float*)d_in[0];
    const int*   gq = (const int*)  d_in[1];
    const float* gs = (const float*)d_in[2];
    const float* gz = (const float*)d_in[3];
    const int*   uq = (const int*)  d_in[4];
    const float* us = (const float*)d_in[5];
    const float* uz = (const float*)d_in[6];
    const int*   dq = (const int*)  d_in[7];
    const float* ds = (const float*)d_in[8];
    const float* dz = (const float*)d_in[9];
    float* out = (float*)d_out;

    static __half *xh_p, *wg_p, *wu_p, *wd_p, *t1_p, *h_p;
    static bool init_done = false;
    if (!init_done) {
        cudaGetSymbolAddress((void**)&xh_p, g_xh);
        cudaGetSymbolAddress((void**)&wg_p, g_Wg);
        cudaGetSymbolAddress((void**)&wu_p, g_Wu);
        cudaGetSymbolAddress((void**)&wd_p, g_Wd);
        cudaGetSymbolAddress((void**)&t1_p, g_t1);
        cudaGetSymbolAddress((void**)&h_p,  g_h);
        cudaFuncSetAttribute(gemm_hmma<0>, cudaFuncAttributeMaxDynamicSharedMemorySize, GEMM_SMEM);
        cudaFuncSetAttribute(gemm_hmma<1>, cudaFuncAttributeMaxDynamicSharedMemorySize, GEMM_SMEM);
        cudaFuncSetAttribute(gemm_hmma<2>, cudaFuncAttributeMaxDynamicSharedMemorySize, GEMM_SMEM);
        init_done = true;
    }

    // Prepass: x -> fp16, weights -> dequantized fp16 K-major (transposed)
    cvt_x_kernel<<<(M_DIM * D_DIM) / (256 * 4), 256>>>(x);
    dequant_t_kernel<<<dim3(I_DIM / 32, D_DIM / 32), dim3(32, 8)>>>(gq, gs, gz, wg_p, D_DIM, I_DIM);
    dequant_t_kernel<<<dim3(I_DIM / 32, D_DIM / 32), dim3(32, 8)>>>(uq, us, uz, wu_p, D_DIM, I_DIM);
    dequant_t_kernel<<<dim3(D_DIM / 32, I_DIM / 32), dim3(32, 8)>>>(dq, ds, dz, wd_p, I_DIM, D_DIM);

    // gate = x @ Wg  -> g_t1 (fp16, pre-activation)
    gemm_hmma<0><<<dim3(M_DIM / 256, I_DIM / 128), 256, GEMM_SMEM>>>(
        xh_p, wg_p, (void*)t1_p, nullptr, D_DIM, I_DIM);
    // up GEMM with fused silu:  h = silu(gate) * (x @ Wu)  -> g_h (fp16)
    gemm_hmma<1><<<dim3(M_DIM / 256, I_DIM / 128), 256, GEMM_SMEM>>>(
        xh_p, wu_p, (void*)h_p, t1_p, D_DIM, I_DIM);
    // out = h @ Wd -> fp32
    gemm_hmma<2><<<dim3(M_DIM / 256, D_DIM / 128), 256, GEMM_SMEM>>>(
        h_p, wd_p, (void*)out, nullptr, I_DIM, D_DIM);
}

// round 9
// speedup vs baseline: 1.3866x; 1.0164x over previous
#include <cuda_runtime.h>
#include <cuda_fp16.h>
#include <cstdint>

// ---------------- Problem dims (fixed by the dataset) ----------------
#define D_DIM 4096
#define I_DIM 11008
#define M_DIM 8192          // 4 * 2048 tokens

// ---------------- Scratch (device globals: allocation-free) ----------
__device__ __half g_xh[(size_t)M_DIM * D_DIM];     //  64 MB  x in fp16 [M, D]
__device__ __half g_Wg[(size_t)I_DIM * D_DIM];     //  90 MB  gate W^T [I, D] (K-major)
__device__ __half g_Wu[(size_t)I_DIM * D_DIM];     //  90 MB  up   W^T [I, D]
__device__ __half g_Wd[(size_t)D_DIM * I_DIM];     //  90 MB  down W^T [D, I]
__device__ __half g_t1[(size_t)M_DIM * I_DIM];     // 176 MB  gate pre-activation fp16
__device__ __half g_h [(size_t)M_DIM * I_DIM];     // 176 MB  h = silu(gate)*up [M, I]

// ---------------- helpers ----------------------------------------
__device__ __forceinline__ uint32_t smem_u32(const void* p) {
    uint32_t a;
    asm("{ .reg .u64 t; cvta.to.shared.u64 t, %1; cvt.u32.u64 %0, t; }" : "=r"(a) : "l"(p));
    return a;
}
__device__ __forceinline__ void cp16(uint32_t s, const void* g) {
    asm volatile("cp.async.cg.shared.global [%0], [%1], 16;" :: "r"(s), "l"(g));
}
#define CP_COMMIT() asm volatile("cp.async.commit_group;" ::: "memory")
#define CP_WAIT0()  asm volatile("cp.async.wait_group 0;" ::: "memory")

#define LDSM_X4(r, addr) \
    asm volatile("ldmatrix.sync.aligned.m8n8.x4.shared.b16 {%0,%1,%2,%3}, [%4];" \
        : "=r"((r)[0]), "=r"((r)[1]), "=r"((r)[2]), "=r"((r)[3]) : "r"(addr))

__device__ __forceinline__ void mma16816(float* c, const uint32_t* a,
                                         uint32_t b0, uint32_t b1) {
    asm volatile(
        "mma.sync.aligned.m16n8k16.row.col.f32.f16.f16.f32 "
        "{%0,%1,%2,%3}, {%4,%5,%6,%7}, {%8,%9}, {%0,%1,%2,%3};"
        : "+f"(c[0]), "+f"(c[1]), "+f"(c[2]), "+f"(c[3])
        : "r"(a[0]), "r"(a[1]), "r"(a[2]), "r"(a[3]), "r"(b0), "r"(b1));
}

// ---------------- Prepass kernels -------------------------------------
__global__ void cvt_x_kernel(const float* __restrict__ x) {
    size_t i = ((size_t)blockIdx.x * blockDim.x + threadIdx.x) * 4;
    float4 v = *(const float4*)(x + i);
    __half2* o = (__half2*)(g_xh + i);
    o[0] = __floats2half2_rn(v.x, v.y);
    o[1] = __floats2half2_rn(v.z, v.w);
}

// q:[K,N] int32 (0..15), s/z:[K/128,N].  Out: Wt[N,K] fp16, Wt[n,k] = (q[k,n]-8)*s+z
__global__ void dequant_t_kernel(const int* __restrict__ q, const float* __restrict__ s,
                                 const float* __restrict__ z, __half* __restrict__ Wt,
                                 int K, int N) {
    __shared__ __half tile[32][33];
    int n0 = blockIdx.x * 32, k0 = blockIdx.y * 32;
    int tx = threadIdx.x, ty = threadIdx.y;          // block (32, 8)
    int n = n0 + tx;
    int grp = k0 >> 7;                               // whole 32-row tile in one group
    float sv = s[(size_t)grp * N + n];
    float zv = z[(size_t)grp * N + n];
#pragma unroll
    for (int i = 0; i < 4; i++) {
        int k = k0 + ty + i * 8;
        int qv = q[(size_t)k * N + n];
        tile[ty + i * 8][tx] = __float2half((float)(qv - 8) * sv + zv);
    }
    __syncthreads();
#pragma unroll
    for (int i = 0; i < 4; i++) {
        int nn = n0 + ty + i * 8;
        Wt[(size_t)nn * K + k0 + tx] = tile[tx][ty + i * 8];
    }
}

// ---------------- HMMA GEMM ----------------------------------------
// C[M,N] = A[M,K] @ B[N,K]^T.  A,B fp16 K-major.
// CTA tile 256x128, BK=128, 256 threads = 8 warps (4 along M x 2 along N),
// warp tile 64x64.  2-stage cp.async double buffer, 272B SMEM row pitch.
// Software-pipelined: ldmatrix frags double-buffered across ks steps;
// next-stage cp.async issued after the first MMA block; 1 barrier/iter.
// MODE 0: store fp16 raw (gate).  MODE 1: h = silu(aux)*acc, fp16 (up+silu).
// MODE 2: store fp32 (down output).
static constexpr int ROW_PITCH = 272;
static constexpr int A_BYTES   = 256 * ROW_PITCH;        // 69632
static constexpr int STAGE_B   = 384 * ROW_PITCH;        // 104448
static constexpr int GEMM_SMEM = 2 * STAGE_B;            // 208896

template <int MODE>
__global__ void __launch_bounds__(256, 1)
gemm_hmma(const __half* __restrict__ Ag, const __half* __restrict__ Bg,
          void* __restrict__ Cg, const __half* __restrict__ aux,
          int K, int N) {
    extern __shared__ char smem[];
    uint32_t sb = smem_u32(smem);
    int tid = threadIdx.x;
    int lane = tid & 31, warp = tid >> 5;
    int wm = (warp & 3) * 64;        // warp M offset in tile (0..192)
    int wn = (warp >> 2) * 64;       // warp N offset in tile (0 or 64)
    int m0 = blockIdx.x * 256;
    int n0 = blockIdx.y * 128;

    const __half* gA = Ag + (size_t)m0 * K;
    const __half* gB = Bg + (size_t)n0 * K;

    auto load_stage = [&](int s, int k0) {
        uint32_t sa = sb + (uint32_t)s * STAGE_B;
#pragma unroll
        for (int i = 0; i < 16; i++) {                // A: 256 rows x 256B
            int id = tid + i * 256;
            int r = id >> 4, c = id & 15;
            cp16(sa + r * ROW_PITCH + c * 16, gA + (size_t)r * K + k0 + c * 8);
        }
#pragma unroll
        for (int i = 0; i < 8; i++) {                 // B: 128 rows x 256B
            int id = tid + i * 256;
            int r = id >> 4, c = id & 15;
            cp16(sa + A_BYTES + r * ROW_PITCH + c * 16, gB + (size_t)r * K + k0 + c * 8);
        }
        CP_COMMIT();
    };

    // per-thread constant parts of ldmatrix addresses
    uint32_t a_row = (uint32_t)((wm + (lane & 15)) * ROW_PITCH) + (uint32_t)((lane >> 4) * 16);
    uint32_t b_row = (uint32_t)((wn + (lane & 7) + ((lane >> 4) & 1) * 8) * ROW_PITCH)
                   + (uint32_t)(((lane >> 3) & 1) * 16);

    auto load_frags = [&](uint32_t sa, uint32_t sB, int ks,
                          uint32_t (*a)[4], uint32_t (*b)[4]) {
        uint32_t ko = (uint32_t)(ks * 32);            // ks*16 halfs = 32 bytes
#pragma unroll
        for (int mi = 0; mi < 4; mi++)
            LDSM_X4(a[mi], sa + a_row + (uint32_t)(mi * 16 * ROW_PITCH) + ko);
#pragma unroll
        for (int bi = 0; bi < 4; bi++)
            LDSM_X4(b[bi], sB + b_row + (uint32_t)(bi * 16 * ROW_PITCH) + ko);
    };

    float acc[4][8][4];
#pragma unroll
    for (int i = 0; i < 4; i++)
#pragma unroll
        for (int j = 0; j < 8; j++)
#pragma unroll
            for (int l = 0; l < 4; l++) acc[i][j][l] = 0.0f;

    load_stage(0, 0);

    int nk = K / 128;
    uint32_t fa[2][4][4], fb[2][4][4];
#pragma unroll 1
    for (int k = 0; k < nk; k++) {
        CP_WAIT0();                                   // stage k resident
        __syncthreads();                              // all warps past reads of other buf

        uint32_t sa = sb + (uint32_t)(k & 1) * STAGE_B;
        uint32_t sB = sa + A_BYTES;

        load_frags(sa, sB, 0, fa[0], fb[0]);          // prime ks=0
#pragma unroll
        for (int ks = 0; ks < 8; ks++) {
            int cur = ks & 1, nxt = cur ^ 1;
            if (ks < 7) load_frags(sa, sB, ks + 1, fa[nxt], fb[nxt]);
            if (ks == 1 && k + 1 < nk)                // prefetch next stage mid-compute
                load_stage((k + 1) & 1, (k + 1) * 128);
#pragma unroll
            for (int mi = 0; mi < 4; mi++)
#pragma unroll
                for (int bi = 0; bi < 4; bi++) {
                    mma16816(acc[mi][2 * bi],     fa[cur][mi], fb[cur][bi][0], fb[cur][bi][1]);
                    mma16816(acc[mi][2 * bi + 1], fa[cur][mi], fb[cur][bi][2], fb[cur][bi][3]);
                }
        }
    }

    // ---- epilogue ----
    int r0 = m0 + wm + (lane >> 2);
    int c0 = n0 + wn + (lane & 3) * 2;
#pragma unroll
    for (int mi = 0; mi < 4; mi++) {
#pragma unroll
        for (int hi = 0; hi < 2; hi++) {
            int row = r0 + mi * 16 + hi * 8;
#pragma unroll
            for (int ni = 0; ni < 8; ni++) {
                int col = c0 + ni * 8;
                float v0 = acc[mi][ni][2 * hi], v1 = acc[mi][ni][2 * hi + 1];
                if (MODE == 0) {
                    *(__half2*)((__half*)Cg + (size_t)row * N + col) =
                        __floats2half2_rn(v0, v1);
                } else if (MODE == 1) {
                    __half2 gh = *(const __half2*)(aux + (size_t)row * N + col);
                    float g0 = __half2float(gh.x), g1 = __half2float(gh.y);
                    float h0 = g0 / (1.0f + __expf(-g0)) * v0;
                    float h1 = g1 / (1.0f + __expf(-g1)) * v1;
                    *(__half2*)((__half*)Cg + (size_t)row * N + col) =
                        __floats2half2_rn(h0, h1);
                } else {
                    *(float2*)((float*)Cg + (size_t)row * N + col) =
                        make_float2(v0, v1);
                }
            }
        }
    }
}

// ---------------- Launch ----------------------------------------------
extern "C" void kernel_launch(void* const* d_in, const int* in_sizes, int n_in,
                              void* d_out, int out_size) {
    (void)in_sizes; (void)n_in; (void)out_size;
    const float* x  = (const float*)d_in[0];
    const int*   gq = (const int*)  d_in[1];
    const float* gs = (const float*)d_in[2];
    const float* gz = (const float*)d_in[3];
    const int*   uq = (const int*)  d_in[4];
    const float* us = (const float*)d_in[5];
    const float* uz = (const float*)d_in[6];
    const int*   dq = (const int*)  d_in[7];
    const float* ds = (const float*)d_in[8];
    const float* dz = (const float*)d_in[9];
    float* out = (float*)d_out;

    static __half *xh_p, *wg_p, *wu_p, *wd_p, *t1_p, *h_p;
    static bool init_done = false;
    if (!init_done) {
        cudaGetSymbolAddress((void**)&xh_p, g_xh);
        cudaGetSymbolAddress((void**)&wg_p, g_Wg);
        cudaGetSymbolAddress((void**)&wu_p, g_Wu);
        cudaGetSymbolAddress((void**)&wd_p, g_Wd);
        cudaGetSymbolAddress((void**)&t1_p, g_t1);
        cudaGetSymbolAddress((void**)&h_p,  g_h);
        cudaFuncSetAttribute(gemm_hmma<0>, cudaFuncAttributeMaxDynamicSharedMemorySize, GEMM_SMEM);
        cudaFuncSetAttribute(gemm_hmma<1>, cudaFuncAttributeMaxDynamicSharedMemorySize, GEMM_SMEM);
        cudaFuncSetAttribute(gemm_hmma<2>, cudaFuncAttributeMaxDynamicSharedMemorySize, GEMM_SMEM);
        init_done = true;
    }

    // Prepass: x -> fp16, weights -> dequantized fp16 K-major (transposed)
    cvt_x_kernel<<<(M_DIM * D_DIM) / (256 * 4), 256>>>(x);
    dequant_t_kernel<<<dim3(I_DIM / 32, D_DIM / 32), dim3(32, 8)>>>(gq, gs, gz, wg_p, D_DIM, I_DIM);
    dequant_t_kernel<<<dim3(I_DIM / 32, D_DIM / 32), dim3(32, 8)>>>(uq, us, uz, wu_p, D_DIM, I_DIM);
    dequant_t_kernel<<<dim3(D_DIM / 32, I_DIM / 32), dim3(32, 8)>>>(dq, ds, dz, wd_p, I_DIM, D_DIM);

    // gate = x @ Wg  -> g_t1 (fp16, pre-activation)
    gemm_hmma<0><<<dim3(M_DIM / 256, I_DIM / 128), 256, GEMM_SMEM>>>(
        xh_p, wg_p, (void*)t1_p, nullptr, D_DIM, I_DIM);
    // up GEMM with fused silu:  h = silu(gate) * (x @ Wu)  -> g_h (fp16)
    gemm_hmma<1><<<dim3(M_DIM / 256, I_DIM / 128), 256, GEMM_SMEM>>>(
        xh_p, wu_p, (void*)h_p, t1_p, D_DIM, I_DIM);
    // out = h @ Wd -> fp32
    gemm_hmma<2><<<dim3(M_DIM / 256, D_DIM / 128), 256, GEMM_SMEM>>>(
        h_p, wd_p, (void*)out, nullptr, I_DIM, D_DIM);
}

// round 13
// speedup vs baseline: 1.4437x; 1.0411x over previous
#include <cuda_runtime.h>
#include <cuda_fp16.h>
#include <cstdint>

// ---------------- Problem dims (fixed by the dataset) ----------------
#define D_DIM 4096
#define I_DIM 11008
#define M_DIM 8192          // 4 * 2048 tokens

// ---------------- Scratch (device globals: allocation-free) ----------
__device__ __half g_xh[(size_t)M_DIM * D_DIM];     //  64 MB  x in fp16 [M, D]
__device__ __half g_Wg[(size_t)I_DIM * D_DIM];     //  90 MB  gate W^T [I, D] (K-major)
__device__ __half g_Wu[(size_t)I_DIM * D_DIM];     //  90 MB  up   W^T [I, D]
__device__ __half g_Wd[(size_t)D_DIM * I_DIM];     //  90 MB  down W^T [D, I]
__device__ __half g_t1[(size_t)M_DIM * I_DIM];     // 176 MB  gate pre-activation fp16
__device__ __half g_h [(size_t)M_DIM * I_DIM];     // 176 MB  h = silu(gate)*up [M, I]

// ---------------- helpers ----------------------------------------
__device__ __forceinline__ uint32_t smem_u32(const void* p) {
    uint32_t a;
    asm("{ .reg .u64 t; cvta.to.shared.u64 t, %1; cvt.u32.u64 %0, t; }" : "=r"(a) : "l"(p));
    return a;
}
__device__ __forceinline__ void cp16(uint32_t s, const void* g) {
    asm volatile("cp.async.cg.shared.global [%0], [%1], 16;" :: "r"(s), "l"(g));
}
#define CP_COMMIT() asm volatile("cp.async.commit_group;" ::: "memory")
#define CP_WAIT0()  asm volatile("cp.async.wait_group 0;" ::: "memory")

#define LDSM_X4(r, addr) \
    asm volatile("ldmatrix.sync.aligned.m8n8.x4.shared.b16 {%0,%1,%2,%3}, [%4];" \
        : "=r"((r)[0]), "=r"((r)[1]), "=r"((r)[2]), "=r"((r)[3]) : "r"(addr))

__device__ __forceinline__ void mma16816(float* c, const uint32_t* a,
                                         uint32_t b0, uint32_t b1) {
    asm volatile(
        "mma.sync.aligned.m16n8k16.row.col.f32.f16.f16.f32 "
        "{%0,%1,%2,%3}, {%4,%5,%6,%7}, {%8,%9}, {%0,%1,%2,%3};"
        : "+f"(c[0]), "+f"(c[1]), "+f"(c[2]), "+f"(c[3])
        : "r"(a[0]), "r"(a[1]), "r"(a[2]), "r"(a[3]), "r"(b0), "r"(b1));
}

// ---------------- Prepass kernels -------------------------------------
__global__ void cvt_x_kernel(const float* __restrict__ x) {
    size_t i = ((size_t)blockIdx.x * blockDim.x + threadIdx.x) * 4;
    float4 v = *(const float4*)(x + i);
    __half2* o = (__half2*)(g_xh + i);
    o[0] = __floats2half2_rn(v.x, v.y);
    o[1] = __floats2half2_rn(v.z, v.w);
}

// q:[K,N] int32 (0..15), s/z:[K/128,N].  Out: Wt[N,K] fp16, Wt[n,k] = (q[k,n]-8)*s+z
__global__ void dequant_t_kernel(const int* __restrict__ q, const float* __restrict__ s,
                                 const float* __restrict__ z, __half* __restrict__ Wt,
                                 int K, int N) {
    __shared__ __half tile[32][33];
    int n0 = blockIdx.x * 32, k0 = blockIdx.y * 32;
    int tx = threadIdx.x, ty = threadIdx.y;          // block (32, 8)
    int n = n0 + tx;
    int grp = k0 >> 7;                               // whole 32-row tile in one group
    float sv = s[(size_t)grp * N + n];
    float zv = z[(size_t)grp * N + n];
#pragma unroll
    for (int i = 0; i < 4; i++) {
        int k = k0 + ty + i * 8;
        int qv = q[(size_t)k * N + n];
        tile[ty + i * 8][tx] = __float2half((float)(qv - 8) * sv + zv);
    }
    __syncthreads();
#pragma unroll
    for (int i = 0; i < 4; i++) {
        int nn = n0 + ty + i * 8;
        Wt[(size_t)nn * K + k0 + tx] = tile[tx][ty + i * 8];
    }
}

// ---------------- HMMA GEMM ----------------------------------------
// C[M,N] = A[M,K] @ B[N,K]^T.  A,B fp16 K-major.
// CTA tile 256x128, BK=128, 512 threads = 16 warps (4 along M x 4 along N),
// warp tile 64x32 -> 4 warps per SMSP for issue-gap coverage.
// 2-stage cp.async double buffer, 272B SMEM row pitch.
// MODE 0: store fp16 raw (gate).  MODE 1: h = silu(aux)*acc, fp16 (up+silu).
// MODE 2: store fp32 (down output).
static constexpr int ROW_PITCH = 272;
static constexpr int A_BYTES   = 256 * ROW_PITCH;        // 69632
static constexpr int STAGE_B   = 384 * ROW_PITCH;        // 104448
static constexpr int GEMM_SMEM = 2 * STAGE_B;            // 208896

template <int MODE>
__global__ void __launch_bounds__(512, 1)
gemm_hmma(const __half* __restrict__ Ag, const __half* __restrict__ Bg,
          void* __restrict__ Cg, const __half* __restrict__ aux,
          int K, int N) {
    extern __shared__ char smem[];
    uint32_t sb = smem_u32(smem);
    int tid = threadIdx.x;
    int lane = tid & 31, warp = tid >> 5;
    int wm = (warp & 3) * 64;        // warp M offset in tile (0..192)
    int wn = (warp >> 2) * 32;       // warp N offset in tile (0..96)
    int m0 = blockIdx.x * 256;
    int n0 = blockIdx.y * 128;

    const __half* gA = Ag + (size_t)m0 * K;
    const __half* gB = Bg + (size_t)n0 * K;

    auto load_stage = [&](int s, int k0) {
        uint32_t sa = sb + (uint32_t)s * STAGE_B;
#pragma unroll
        for (int i = 0; i < 8; i++) {                 // A: 256 rows x 256B
            int id = tid + i * 512;
            int r = id >> 4, c = id & 15;
            cp16(sa + r * ROW_PITCH + c * 16, gA + (size_t)r * K + k0 + c * 8);
        }
#pragma unroll
        for (int i = 0; i < 4; i++) {                 // B: 128 rows x 256B
            int id = tid + i * 512;
            int r = id >> 4, c = id & 15;
            cp16(sa + A_BYTES + r * ROW_PITCH + c * 16, gB + (size_t)r * K + k0 + c * 8);
        }
        CP_COMMIT();
    };

    // per-thread constant parts of ldmatrix addresses
    uint32_t a_row = (uint32_t)((wm + (lane & 15)) * ROW_PITCH) + (uint32_t)((lane >> 4) * 16);
    uint32_t b_row = (uint32_t)((wn + (lane & 7) + ((lane >> 4) & 1) * 8) * ROW_PITCH)
                   + (uint32_t)(((lane >> 3) & 1) * 16);

    float acc[4][4][4];
#pragma unroll
    for (int i = 0; i < 4; i++)
#pragma unroll
        for (int j = 0; j < 4; j++)
#pragma unroll
            for (int l = 0; l < 4; l++) acc[i][j][l] = 0.0f;

    load_stage(0, 0);

    int nk = K / 128;
#pragma unroll 1
    for (int k = 0; k < nk; k++) {
        CP_WAIT0();                                   // stage k resident
        __syncthreads();                              // all warps done reading other buf
        if (k + 1 < nk)                               // prefetch next stage
            load_stage((k + 1) & 1, (k + 1) * 128);

        uint32_t sa = sb + (uint32_t)(k & 1) * STAGE_B;
        uint32_t sB = sa + A_BYTES;
#pragma unroll
        for (int ks = 0; ks < 8; ks++) {
            uint32_t ko = (uint32_t)(ks * 32);
            uint32_t a[4][4], b[2][4];
#pragma unroll
            for (int mi = 0; mi < 4; mi++)
                LDSM_X4(a[mi], sa + a_row + (uint32_t)(mi * 16 * ROW_PITCH) + ko);
#pragma unroll
            for (int bi = 0; bi < 2; bi++)
                LDSM_X4(b[bi], sB + b_row + (uint32_t)(bi * 16 * ROW_PITCH) + ko);
#pragma unroll
            for (int mi = 0; mi < 4; mi++)
#pragma unroll
                for (int bi = 0; bi < 2; bi++) {
                    mma16816(acc[mi][2 * bi],     a[mi], b[bi][0], b[bi][1]);
                    mma16816(acc[mi][2 * bi + 1], a[mi], b[bi][2], b[bi][3]);
                }
        }
    }

    // ---- epilogue ----
    int r0 = m0 + wm + (lane >> 2);
    int c0 = n0 + wn + (lane & 3) * 2;
#pragma unroll
    for (int mi = 0; mi < 4; mi++) {
#pragma unroll
        for (int hi = 0; hi < 2; hi++) {
            int row = r0 + mi * 16 + hi * 8;
#pragma unroll
            for (int ni = 0; ni < 4; ni++) {
                int col = c0 + ni * 8;
                float v0 = acc[mi][ni][2 * hi], v1 = acc[mi][ni][2 * hi + 1];
                if (MODE == 0) {
                    *(__half2*)((__half*)Cg + (size_t)row * N + col) =
                        __floats2half2_rn(v0, v1);
                } else if (MODE == 1) {
                    __half2 gh = *(const __half2*)(aux + (size_t)row * N + col);
                    float g0 = __half2float(gh.x), g1 = __half2float(gh.y);
                    float h0 = g0 / (1.0f + __expf(-g0)) * v0;
                    float h1 = g1 / (1.0f + __expf(-g1)) * v1;
                    *(__half2*)((__half*)Cg + (size_t)row * N + col) =
                        __floats2half2_rn(h0, h1);
                } else {
                    *(float2*)((float*)Cg + (size_t)row * N + col) =
                        make_float2(v0, v1);
                }
            }
        }
    }
}

// ---------------- Launch ----------------------------------------------
extern "C" void kernel_launch(void* const* d_in, const int* in_sizes, int n_in,
                              void* d_out, int out_size) {
    (void)in_sizes; (void)n_in; (void)out_size;
    const float* x  = (const float*)d_in[0];
    const int*   gq = (const int*)  d_in[1];
    const float* gs = (const float*)d_in[2];
    const float* gz = (const float*)d_in[3];
    const int*   uq = (const int*)  d_in[4];
    const float* us = (const float*)d_in[5];
    const float* uz = (const float*)d_in[6];
    const int*   dq = (const int*)  d_in[7];
    const float* ds = (const float*)d_in[8];
    const float* dz = (const float*)d_in[9];
    float* out = (float*)d_out;

    static __half *xh_p, *wg_p, *wu_p, *wd_p, *t1_p, *h_p;
    static bool init_done = false;
    if (!init_done) {
        cudaGetSymbolAddress((void**)&xh_p, g_xh);
        cudaGetSymbolAddress((void**)&wg_p, g_Wg);
        cudaGetSymbolAddress((void**)&wu_p, g_Wu);
        cudaGetSymbolAddress((void**)&wd_p, g_Wd);
        cudaGetSymbolAddress((void**)&t1_p, g_t1);
        cudaGetSymbolAddress((void**)&h_p,  g_h);
        cudaFuncSetAttribute(gemm_hmma<0>, cudaFuncAttributeMaxDynamicSharedMemorySize, GEMM_SMEM);
        cudaFuncSetAttribute(gemm_hmma<1>, cudaFuncAttributeMaxDynamicSharedMemorySize, GEMM_SMEM);
        cudaFuncSetAttribute(gemm_hmma<2>, cudaFuncAttributeMaxDynamicSharedMemorySize, GEMM_SMEM);
        init_done = true;
    }

    // Prepass: x -> fp16, weights -> dequantized fp16 K-major (transposed)
    cvt_x_kernel<<<(M_DIM * D_DIM) / (256 * 4), 256>>>(x);
    dequant_t_kernel<<<dim3(I_DIM / 32, D_DIM / 32), dim3(32, 8)>>>(gq, gs, gz, wg_p, D_DIM, I_DIM);
    dequant_t_kernel<<<dim3(I_DIM / 32, D_DIM / 32), dim3(32, 8)>>>(uq, us, uz, wu_p, D_DIM, I_DIM);
    dequant_t_kernel<<<dim3(D_DIM / 32, I_DIM / 32), dim3(32, 8)>>>(dq, ds, dz, wd_p, I_DIM, D_DIM);

    // gate = x @ Wg  -> g_t1 (fp16, pre-activation)
    gemm_hmma<0><<<dim3(M_DIM / 256, I_DIM / 128), 512, GEMM_SMEM>>>(
        xh_p, wg_p, (void*)t1_p, nullptr, D_DIM, I_DIM);
    // up GEMM with fused silu:  h = silu(gate) * (x @ Wu)  -> g_h (fp16)
    gemm_hmma<1><<<dim3(M_DIM / 256, I_DIM / 128), 512, GEMM_SMEM>>>(
        xh_p, wu_p, (void*)h_p, t1_p, D_DIM, I_DIM);
    // out = h @ Wd -> fp32
    gemm_hmma<2><<<dim3(M_DIM / 256, D_DIM / 128), 512, GEMM_SMEM>>>(
        h_p, wd_p, (void*)out, nullptr, I_DIM, D_DIM);
}

// round 14
// speedup vs baseline: 1.4739x; 1.0210x over previous
#include <cuda_runtime.h>
#include <cuda_fp16.h>
#include <cstdint>

// ---------------- Problem dims (fixed by the dataset) ----------------
#define D_DIM 4096
#define I_DIM 11008
#define M_DIM 8192          // 4 * 2048 tokens

// ---------------- Scratch (device globals: allocation-free) ----------
__device__ __half g_xh[(size_t)M_DIM * D_DIM];     //  64 MB  x in fp16 [M, D]
__device__ __half g_Wg[(size_t)I_DIM * D_DIM];     //  90 MB  gate W^T [I, D] (K-major)
__device__ __half g_Wu[(size_t)I_DIM * D_DIM];     //  90 MB  up   W^T [I, D]
__device__ __half g_Wd[(size_t)D_DIM * I_DIM];     //  90 MB  down W^T [D, I]
__device__ __half g_t1[(size_t)M_DIM * I_DIM];     // 176 MB  gate pre-activation fp16
__device__ __half g_h [(size_t)M_DIM * I_DIM];     // 176 MB  h = silu(gate)*up [M, I]

// ---------------- helpers ----------------------------------------
__device__ __forceinline__ uint32_t smem_u32(const void* p) {
    uint32_t a;
    asm("{ .reg .u64 t; cvta.to.shared.u64 t, %1; cvt.u32.u64 %0, t; }" : "=r"(a) : "l"(p));
    return a;
}
__device__ __forceinline__ void cp16(uint32_t s, const void* g) {
    asm volatile("cp.async.cg.shared.global [%0], [%1], 16;" :: "r"(s), "l"(g));
}
#define CP_COMMIT() asm volatile("cp.async.commit_group;" ::: "memory")
#define CP_WAIT1()  asm volatile("cp.async.wait_group 1;" ::: "memory")

#define LDSM_X4(r, addr) \
    asm volatile("ldmatrix.sync.aligned.m8n8.x4.shared.b16 {%0,%1,%2,%3}, [%4];" \
        : "=r"((r)[0]), "=r"((r)[1]), "=r"((r)[2]), "=r"((r)[3]) : "r"(addr))

__device__ __forceinline__ void mma16816(float* c, const uint32_t* a,
                                         uint32_t b0, uint32_t b1) {
    asm volatile(
        "mma.sync.aligned.m16n8k16.row.col.f32.f16.f16.f32 "
        "{%0,%1,%2,%3}, {%4,%5,%6,%7}, {%8,%9}, {%0,%1,%2,%3};"
        : "+f"(c[0]), "+f"(c[1]), "+f"(c[2]), "+f"(c[3])
        : "r"(a[0]), "r"(a[1]), "r"(a[2]), "r"(a[3]), "r"(b0), "r"(b1));
}

// ---------------- Prepass kernels -------------------------------------
__global__ void cvt_x_kernel(const float* __restrict__ x) {
    size_t i = ((size_t)blockIdx.x * blockDim.x + threadIdx.x) * 4;
    float4 v = *(const float4*)(x + i);
    __half2* o = (__half2*)(g_xh + i);
    o[0] = __floats2half2_rn(v.x, v.y);
    o[1] = __floats2half2_rn(v.z, v.w);
}

// q:[K,N] int32 (0..15), s/z:[K/128,N].  Out: Wt[N,K] fp16, Wt[n,k] = (q[k,n]-8)*s+z
__global__ void dequant_t_kernel(const int* __restrict__ q, const float* __restrict__ s,
                                 const float* __restrict__ z, __half* __restrict__ Wt,
                                 int K, int N) {
    __shared__ __half tile[32][33];
    int n0 = blockIdx.x * 32, k0 = blockIdx.y * 32;
    int tx = threadIdx.x, ty = threadIdx.y;          // block (32, 8)
    int n = n0 + tx;
    int grp = k0 >> 7;                               // whole 32-row tile in one group
    float sv = s[(size_t)grp * N + n];
    float zv = z[(size_t)grp * N + n];
#pragma unroll
    for (int i = 0; i < 4; i++) {
        int k = k0 + ty + i * 8;
        int qv = q[(size_t)k * N + n];
        tile[ty + i * 8][tx] = __float2half((float)(qv - 8) * sv + zv);
    }
    __syncthreads();
#pragma unroll
    for (int i = 0; i < 4; i++) {
        int nn = n0 + ty + i * 8;
        Wt[(size_t)nn * K + k0 + tx] = tile[tx][ty + i * 8];
    }
}

// ---------------- HMMA GEMM ----------------------------------------
// C[M,N] = A[M,K] @ B[N,K]^T.  A,B fp16 K-major.
// CTA tile 128x128, BK=64, 256 threads = 8 warps (2 along M x 4 along N),
// warp tile 64x32.  3-stage cp.async pipeline, 144B SMEM row pitch.
// __launch_bounds__(256, 2): 2 CTAs/SM -> decoupled barriers cover
// wait/sync stalls (reg cap 128, smem 108KB/CTA, 216KB/SM).
// MODE 0: store fp16 raw (gate).  MODE 1: h = silu(aux)*acc, fp16 (up+silu).
// MODE 2: store fp32 (down output).
static constexpr int ROW_PITCH = 144;
static constexpr int A_BYTES   = 128 * ROW_PITCH;        // 18432
static constexpr int STAGE_B   = 256 * ROW_PITCH;        // 36864
static constexpr int GEMM_SMEM = 3 * STAGE_B;            // 110592

template <int MODE>
__global__ void __launch_bounds__(256, 2)
gemm_hmma(const __half* __restrict__ Ag, const __half* __restrict__ Bg,
          void* __restrict__ Cg, const __half* __restrict__ aux,
          int K, int N) {
    extern __shared__ char smem[];
    uint32_t sb = smem_u32(smem);
    int tid = threadIdx.x;
    int lane = tid & 31, warp = tid >> 5;
    int wm = (warp & 1) * 64;        // warp M offset in tile (0 or 64)
    int wn = (warp >> 1) * 32;       // warp N offset in tile (0..96)
    int m0 = blockIdx.x * 128;
    int n0 = blockIdx.y * 128;

    const __half* gA = Ag + (size_t)m0 * K;
    const __half* gB = Bg + (size_t)n0 * K;

    auto load_stage = [&](int s, int k0) {
        uint32_t sa = sb + (uint32_t)s * STAGE_B;
#pragma unroll
        for (int i = 0; i < 4; i++) {                 // A: 128 rows x 128B
            int id = tid + i * 256;
            int r = id >> 3, c = id & 7;
            cp16(sa + r * ROW_PITCH + c * 16, gA + (size_t)r * K + k0 + c * 8);
        }
#pragma unroll
        for (int i = 0; i < 4; i++) {                 // B: 128 rows x 128B
            int id = tid + i * 256;
            int r = id >> 3, c = id & 7;
            cp16(sa + A_BYTES + r * ROW_PITCH + c * 16, gB + (size_t)r * K + k0 + c * 8);
        }
        CP_COMMIT();
    };

    // per-thread constant parts of ldmatrix addresses
    uint32_t a_row = (uint32_t)((wm + (lane & 15)) * ROW_PITCH) + (uint32_t)((lane >> 4) * 16);
    uint32_t b_row = (uint32_t)((wn + (lane & 7) + ((lane >> 4) & 1) * 8) * ROW_PITCH)
                   + (uint32_t)(((lane >> 3) & 1) * 16);

    float acc[4][4][4];
#pragma unroll
    for (int i = 0; i < 4; i++)
#pragma unroll
        for (int j = 0; j < 4; j++)
#pragma unroll
            for (int l = 0; l < 4; l++) acc[i][j][l] = 0.0f;

    load_stage(0, 0);
    load_stage(1, 64);

    int nk = K / 64;
#pragma unroll 1
    for (int k = 0; k < nk; k++) {
        CP_WAIT1();                                   // stage k resident
        __syncthreads();
        if (k + 2 < nk) {
            load_stage((k + 2) % 3, (k + 2) * 64);
        } else {
            CP_COMMIT();                              // keep group accounting uniform
        }

        uint32_t sa = sb + (uint32_t)(k % 3) * STAGE_B;
        uint32_t sB = sa + A_BYTES;
#pragma unroll
        for (int ks = 0; ks < 4; ks++) {
            uint32_t ko = (uint32_t)(ks * 32);
            uint32_t a[4][4], b[2][4];
#pragma unroll
            for (int mi = 0; mi < 4; mi++)
                LDSM_X4(a[mi], sa + a_row + (uint32_t)(mi * 16 * ROW_PITCH) + ko);
#pragma unroll
            for (int bi = 0; bi < 2; bi++)
                LDSM_X4(b[bi], sB + b_row + (uint32_t)(bi * 16 * ROW_PITCH) + ko);
#pragma unroll
            for (int mi = 0; mi < 4; mi++)
#pragma unroll
                for (int bi = 0; bi < 2; bi++) {
                    mma16816(acc[mi][2 * bi],     a[mi], b[bi][0], b[bi][1]);
                    mma16816(acc[mi][2 * bi + 1], a[mi], b[bi][2], b[bi][3]);
                }
        }
    }

    // ---- epilogue ----
    int r0 = m0 + wm + (lane >> 2);
    int c0 = n0 + wn + (lane & 3) * 2;
#pragma unroll
    for (int mi = 0; mi < 4; mi++) {
#pragma unroll
        for (int hi = 0; hi < 2; hi++) {
            int row = r0 + mi * 16 + hi * 8;
#pragma unroll
            for (int ni = 0; ni < 4; ni++) {
                int col = c0 + ni * 8;
                float v0 = acc[mi][ni][2 * hi], v1 = acc[mi][ni][2 * hi + 1];
                if (MODE == 0) {
                    *(__half2*)((__half*)Cg + (size_t)row * N + col) =
                        __floats2half2_rn(v0, v1);
                } else if (MODE == 1) {
                    __half2 gh = *(const __half2*)(aux + (size_t)row * N + col);
                    float g0 = __half2float(gh.x), g1 = __half2float(gh.y);
                    float h0 = g0 / (1.0f + __expf(-g0)) * v0;
                    float h1 = g1 / (1.0f + __expf(-g1)) * v1;
                    *(__half2*)((__half*)Cg + (size_t)row * N + col) =
                        __floats2half2_rn(h0, h1);
                } else {
                    *(float2*)((float*)Cg + (size_t)row * N + col) =
                        make_float2(v0, v1);
                }
            }
        }
    }
}

// ---------------- Launch ----------------------------------------------
extern "C" void kernel_launch(void* const* d_in, const int* in_sizes, int n_in,
                              void* d_out, int out_size) {
    (void)in_sizes; (void)n_in; (void)out_size;
    const float* x  = (const float*)d_in[0];
    const int*   gq = (const int*)  d_in[1];
    const float* gs = (const float*)d_in[2];
    const float* gz = (const float*)d_in[3];
    const int*   uq = (const int*)  d_in[4];
    const float* us = (const float*)d_in[5];
    const float* uz = (const float*)d_in[6];
    const int*   dq = (const int*)  d_in[7];
    const float* ds = (const float*)d_in[8];
    const float* dz = (const float*)d_in[9];
    float* out = (float*)d_out;

    static __half *xh_p, *wg_p, *wu_p, *wd_p, *t1_p, *h_p;
    static bool init_done = false;
    if (!init_done) {
        cudaGetSymbolAddress((void**)&xh_p, g_xh);
        cudaGetSymbolAddress((void**)&wg_p, g_Wg);
        cudaGetSymbolAddress((void**)&wu_p, g_Wu);
        cudaGetSymbolAddress((void**)&wd_p, g_Wd);
        cudaGetSymbolAddress((void**)&t1_p, g_t1);
        cudaGetSymbolAddress((void**)&h_p,  g_h);
        cudaFuncSetAttribute(gemm_hmma<0>, cudaFuncAttributeMaxDynamicSharedMemorySize, GEMM_SMEM);
        cudaFuncSetAttribute(gemm_hmma<1>, cudaFuncAttributeMaxDynamicSharedMemorySize, GEMM_SMEM);
        cudaFuncSetAttribute(gemm_hmma<2>, cudaFuncAttributeMaxDynamicSharedMemorySize, GEMM_SMEM);
        init_done = true;
    }

    // Prepass: x -> fp16, weights -> dequantized fp16 K-major (transposed)
    cvt_x_kernel<<<(M_DIM * D_DIM) / (256 * 4), 256>>>(x);
    dequant_t_kernel<<<dim3(I_DIM / 32, D_DIM / 32), dim3(32, 8)>>>(gq, gs, gz, wg_p, D_DIM, I_DIM);
    dequant_t_kernel<<<dim3(I_DIM / 32, D_DIM / 32), dim3(32, 8)>>>(uq, us, uz, wu_p, D_DIM, I_DIM);
    dequant_t_kernel<<<dim3(D_DIM / 32, I_DIM / 32), dim3(32, 8)>>>(dq, ds, dz, wd_p, I_DIM, D_DIM);

    // gate = x @ Wg  -> g_t1 (fp16, pre-activation)
    gemm_hmma<0><<<dim3(M_DIM / 128, I_DIM / 128), 256, GEMM_SMEM>>>(
        xh_p, wg_p, (void*)t1_p, nullptr, D_DIM, I_DIM);
    // up GEMM with fused silu:  h = silu(gate) * (x @ Wu)  -> g_h (fp16)
    gemm_hmma<1><<<dim3(M_DIM / 128, I_DIM / 128), 256, GEMM_SMEM>>>(
        xh_p, wu_p, (void*)h_p, t1_p, D_DIM, I_DIM);
    // out = h @ Wd -> fp32
    gemm_hmma<2><<<dim3(M_DIM / 128, D_DIM / 128), 256, GEMM_SMEM>>>(
        h_p, wd_p, (void*)out, nullptr, I_DIM, D_DIM);
}

// round 15
// speedup vs baseline: 1.5212x; 1.0321x over previous
#include <cuda_runtime.h>
#include <cuda_fp16.h>
#include <cstdint>

// ---------------- Problem dims (fixed by the dataset) ----------------
#define D_DIM 4096
#define I_DIM 11008
#define M_DIM 8192          // 4 * 2048 tokens

// ---------------- Scratch (device globals: allocation-free) ----------
__device__ __half g_xh[(size_t)M_DIM * D_DIM];     //  64 MB  x in fp16 [M, D]
__device__ __half g_Wg[(size_t)I_DIM * D_DIM];     //  90 MB  gate W^T [I, D] (K-major)
__device__ __half g_Wu[(size_t)I_DIM * D_DIM];     //  90 MB  up   W^T [I, D]
__device__ __half g_Wd[(size_t)D_DIM * I_DIM];     //  90 MB  down W^T [D, I]
__device__ __half g_h [(size_t)M_DIM * I_DIM];     // 176 MB  h = silu(gate)*up [M, I]

// ---------------- helpers ----------------------------------------
__device__ __forceinline__ uint32_t smem_u32(const void* p) {
    uint32_t a;
    asm("{ .reg .u64 t; cvta.to.shared.u64 t, %1; cvt.u32.u64 %0, t; }" : "=r"(a) : "l"(p));
    return a;
}
__device__ __forceinline__ void cp16(uint32_t s, const void* g) {
    asm volatile("cp.async.cg.shared.global [%0], [%1], 16;" :: "r"(s), "l"(g));
}
#define CP_COMMIT() asm volatile("cp.async.commit_group;" ::: "memory")
#define CP_WAIT1()  asm volatile("cp.async.wait_group 1;" ::: "memory")

#define LDSM_X4(r, addr) \
    asm volatile("ldmatrix.sync.aligned.m8n8.x4.shared.b16 {%0,%1,%2,%3}, [%4];" \
        : "=r"((r)[0]), "=r"((r)[1]), "=r"((r)[2]), "=r"((r)[3]) : "r"(addr))

__device__ __forceinline__ void mma16816(float* c, const uint32_t* a,
                                         uint32_t b0, uint32_t b1) {
    asm volatile(
        "mma.sync.aligned.m16n8k16.row.col.f32.f16.f16.f32 "
        "{%0,%1,%2,%3}, {%4,%5,%6,%7}, {%8,%9}, {%0,%1,%2,%3};"
        : "+f"(c[0]), "+f"(c[1]), "+f"(c[2]), "+f"(c[3])
        : "r"(a[0]), "r"(a[1]), "r"(a[2]), "r"(a[3]), "r"(b0), "r"(b1));
}

// ---------------- Prepass kernels -------------------------------------
__global__ void cvt_x_kernel(const float* __restrict__ x) {
    size_t i = ((size_t)blockIdx.x * blockDim.x + threadIdx.x) * 4;
    float4 v = *(const float4*)(x + i);
    __half2* o = (__half2*)(g_xh + i);
    o[0] = __floats2half2_rn(v.x, v.y);
    o[1] = __floats2half2_rn(v.z, v.w);
}

// q:[K,N] int32 (0..15), s/z:[K/128,N].  Out: Wt[N,K] fp16, Wt[n,k] = (q[k,n]-8)*s+z
__global__ void dequant_t_kernel(const int* __restrict__ q, const float* __restrict__ s,
                                 const float* __restrict__ z, __half* __restrict__ Wt,
                                 int K, int N) {
    __shared__ __half tile[32][33];
    int n0 = blockIdx.x * 32, k0 = blockIdx.y * 32;
    int tx = threadIdx.x, ty = threadIdx.y;          // block (32, 8)
    int n = n0 + tx;
    int grp = k0 >> 7;                               // whole 32-row tile in one group
    float sv = s[(size_t)grp * N + n];
    float zv = z[(size_t)grp * N + n];
#pragma unroll
    for (int i = 0; i < 4; i++) {
        int k = k0 + ty + i * 8;
        int qv = q[(size_t)k * N + n];
        tile[ty + i * 8][tx] = __float2half((float)(qv - 8) * sv + zv);
    }
    __syncthreads();
#pragma unroll
    for (int i = 0; i < 4; i++) {
        int nn = n0 + ty + i * 8;
        Wt[(size_t)nn * K + k0 + tx] = tile[tx][ty + i * 8];
    }
}

// ---------------- Common GEMM constants --------------------------------
// 144B SMEM row pitch (128B data + 16B pad -> conflict-free ldmatrix),
// 3-stage cp.async, BK=64, 256 threads, __launch_bounds__(256, 2).
static constexpr int ROW_PITCH = 144;
static constexpr int STAGE_B   = 256 * ROW_PITCH;        // 36864 (256 rows/stage)
static constexpr int GEMM_SMEM = 3 * STAGE_B;            // 110592

// ---------------- Fused gate+up GEMM + SiLU ----------------------------
// For one CTA: gate/up tiles of 128(M) x 64(N); B region holds Wg rows then
// Wu rows (64 each).  8 warps = 4(M) x 2(N), warp tile 32x32 per matrix.
// Epilogue: g_h = silu(gate) * up   (fp32 accs -> fp16), no intermediate.
static constexpr int A_ROWS_F  = 128;
static constexpr int A_BYTES_F = A_ROWS_F * ROW_PITCH;   // 18432
static constexpr int BU_OFF_F  = A_BYTES_F + 64 * ROW_PITCH;  // Wu rows after Wg

__global__ void __launch_bounds__(256, 2)
gemm_gateup(const __half* __restrict__ Ag, const __half* __restrict__ Bgg,
            const __half* __restrict__ Bug, __half* __restrict__ Hg) {
    extern __shared__ char smem[];
    uint32_t sb = smem_u32(smem);
    int tid = threadIdx.x;
    int lane = tid & 31, warp = tid >> 5;
    int wm = (warp & 3) * 32;        // warp M offset (0..96)
    int wn = (warp >> 2) * 32;       // warp N offset (0 or 32)
    int m0 = blockIdx.x * 128;
    int n0 = blockIdx.y * 64;
    const int K = D_DIM;

    const __half* gA  = Ag  + (size_t)m0 * K;
    const __half* gBg = Bgg + (size_t)n0 * K;
    const __half* gBu = Bug + (size_t)n0 * K;

    auto load_stage = [&](int s, int k0) {
        uint32_t sa = sb + (uint32_t)s * STAGE_B;
#pragma unroll
        for (int i = 0; i < 4; i++) {                 // A: 128 rows x 128B
            int id = tid + i * 256;
            int r = id >> 3, c = id & 7;
            cp16(sa + r * ROW_PITCH + c * 16, gA + (size_t)r * K + k0 + c * 8);
        }
#pragma unroll
        for (int i = 0; i < 2; i++) {                 // Bg: 64 rows x 128B
            int id = tid + i * 256;
            int r = id >> 3, c = id & 7;
            cp16(sa + A_BYTES_F + r * ROW_PITCH + c * 16, gBg + (size_t)r * K + k0 + c * 8);
        }
#pragma unroll
        for (int i = 0; i < 2; i++) {                 // Bu: 64 rows x 128B
            int id = tid + i * 256;
            int r = id >> 3, c = id & 7;
            cp16(sa + BU_OFF_F + r * ROW_PITCH + c * 16, gBu + (size_t)r * K + k0 + c * 8);
        }
        CP_COMMIT();
    };

    uint32_t a_row = (uint32_t)((wm + (lane & 15)) * ROW_PITCH) + (uint32_t)((lane >> 4) * 16);
    uint32_t b_row = (uint32_t)((wn + (lane & 7) + ((lane >> 4) & 1) * 8) * ROW_PITCH)
                   + (uint32_t)(((lane >> 3) & 1) * 16);

    float accg[2][4][4], accu[2][4][4];
#pragma unroll
    for (int i = 0; i < 2; i++)
#pragma unroll
        for (int j = 0; j < 4; j++)
#pragma unroll
            for (int l = 0; l < 4; l++) { accg[i][j][l] = 0.0f; accu[i][j][l] = 0.0f; }

    load_stage(0, 0);
    load_stage(1, 64);

    const int nk = K / 64;
#pragma unroll 1
    for (int k = 0; k < nk; k++) {
        CP_WAIT1();
        __syncthreads();
        if (k + 2 < nk) {
            load_stage((k + 2) % 3, (k + 2) * 64);
        } else {
            CP_COMMIT();
        }

        uint32_t sa  = sb + (uint32_t)(k % 3) * STAGE_B;
        uint32_t sBg = sa + A_BYTES_F;
        uint32_t sBu = sa + BU_OFF_F;
#pragma unroll
        for (int ks = 0; ks < 4; ks++) {
            uint32_t ko = (uint32_t)(ks * 32);
            uint32_t a[2][4], bg[2][4], bu[2][4];
#pragma unroll
            for (int mi = 0; mi < 2; mi++)
                LDSM_X4(a[mi], sa + a_row + (uint32_t)(mi * 16 * ROW_PITCH) + ko);
#pragma unroll
            for (int bi = 0; bi < 2; bi++) {
                LDSM_X4(bg[bi], sBg + b_row + (uint32_t)(bi * 16 * ROW_PITCH) + ko);
                LDSM_X4(bu[bi], sBu + b_row + (uint32_t)(bi * 16 * ROW_PITCH) + ko);
            }
#pragma unroll
            for (int mi = 0; mi < 2; mi++)
#pragma unroll
                for (int bi = 0; bi < 2; bi++) {
                    mma16816(accg[mi][2 * bi],     a[mi], bg[bi][0], bg[bi][1]);
                    mma16816(accg[mi][2 * bi + 1], a[mi], bg[bi][2], bg[bi][3]);
                    mma16816(accu[mi][2 * bi],     a[mi], bu[bi][0], bu[bi][1]);
                    mma16816(accu[mi][2 * bi + 1], a[mi], bu[bi][2], bu[bi][3]);
                }
        }
    }

    // ---- epilogue: h = silu(gate) * up ----
    int r0 = m0 + wm + (lane >> 2);
    int c0 = n0 + wn + (lane & 3) * 2;
#pragma unroll
    for (int mi = 0; mi < 2; mi++) {
#pragma unroll
        for (int hi = 0; hi < 2; hi++) {
            int row = r0 + mi * 16 + hi * 8;
#pragma unroll
            for (int ni = 0; ni < 4; ni++) {
                int col = c0 + ni * 8;
                float g0 = accg[mi][ni][2 * hi], g1 = accg[mi][ni][2 * hi + 1];
                float u0 = accu[mi][ni][2 * hi], u1 = accu[mi][ni][2 * hi + 1];
                float h0 = g0 / (1.0f + __expf(-g0)) * u0;
                float h1 = g1 / (1.0f + __expf(-g1)) * u1;
                *(__half2*)(Hg + (size_t)row * I_DIM + col) = __floats2half2_rn(h0, h1);
            }
        }
    }
}

// ---------------- Down GEMM: out = h @ Wd^T (fp32 out) -----------------
// CTA tile 128x128, BK=64, 8 warps (2 M x 4 N), warp tile 64x32.
static constexpr int A_BYTES_D = 128 * ROW_PITCH;        // 18432

__global__ void __launch_bounds__(256, 2)
gemm_down(const __half* __restrict__ Ag, const __half* __restrict__ Bg,
          float* __restrict__ Cg) {
    extern __shared__ char smem[];
    uint32_t sb = smem_u32(smem);
    int tid = threadIdx.x;
    int lane = tid & 31, warp = tid >> 5;
    int wm = (warp & 1) * 64;
    int wn = (warp >> 1) * 32;
    int m0 = blockIdx.x * 128;
    int n0 = blockIdx.y * 128;
    const int K = I_DIM, N = D_DIM;

    const __half* gA = Ag + (size_t)m0 * K;
    const __half* gB = Bg + (size_t)n0 * K;

    auto load_stage = [&](int s, int k0) {
        uint32_t sa = sb + (uint32_t)s * STAGE_B;
#pragma unroll
        for (int i = 0; i < 4; i++) {
            int id = tid + i * 256;
            int r = id >> 3, c = id & 7;
            cp16(sa + r * ROW_PITCH + c * 16, gA + (size_t)r * K + k0 + c * 8);
        }
#pragma unroll
        for (int i = 0; i < 4; i++) {
            int id = tid + i * 256;
            int r = id >> 3, c = id & 7;
            cp16(sa + A_BYTES_D + r * ROW_PITCH + c * 16, gB + (size_t)r * K + k0 + c * 8);
        }
        CP_COMMIT();
    };

    uint32_t a_row = (uint32_t)((wm + (lane & 15)) * ROW_PITCH) + (uint32_t)((lane >> 4) * 16);
    uint32_t b_row = (uint32_t)((wn + (lane & 7) + ((lane >> 4) & 1) * 8) * ROW_PITCH)
                   + (uint32_t)(((lane >> 3) & 1) * 16);

    float acc[4][4][4];
#pragma unroll
    for (int i = 0; i < 4; i++)
#pragma unroll
        for (int j = 0; j < 4; j++)
#pragma unroll
            for (int l = 0; l < 4; l++) acc[i][j][l] = 0.0f;

    load_stage(0, 0);
    load_stage(1, 64);

    const int nk = K / 64;
#pragma unroll 1
    for (int k = 0; k < nk; k++) {
        CP_WAIT1();
        __syncthreads();
        if (k + 2 < nk) {
            load_stage((k + 2) % 3, (k + 2) * 64);
        } else {
            CP_COMMIT();
        }

        uint32_t sa = sb + (uint32_t)(k % 3) * STAGE_B;
        uint32_t sB = sa + A_BYTES_D;
#pragma unroll
        for (int ks = 0; ks < 4; ks++) {
            uint32_t ko = (uint32_t)(ks * 32);
            uint32_t a[4][4], b[2][4];
#pragma unroll
            for (int mi = 0; mi < 4; mi++)
                LDSM_X4(a[mi], sa + a_row + (uint32_t)(mi * 16 * ROW_PITCH) + ko);
#pragma unroll
            for (int bi = 0; bi < 2; bi++)
                LDSM_X4(b[bi], sB + b_row + (uint32_t)(bi * 16 * ROW_PITCH) + ko);
#pragma unroll
            for (int mi = 0; mi < 4; mi++)
#pragma unroll
                for (int bi = 0; bi < 2; bi++) {
                    mma16816(acc[mi][2 * bi],     a[mi], b[bi][0], b[bi][1]);
                    mma16816(acc[mi][2 * bi + 1], a[mi], b[bi][2], b[bi][3]);
                }
        }
    }

    int r0 = m0 + wm + (lane >> 2);
    int c0 = n0 + wn + (lane & 3) * 2;
#pragma unroll
    for (int mi = 0; mi < 4; mi++) {
#pragma unroll
        for (int hi = 0; hi < 2; hi++) {
            int row = r0 + mi * 16 + hi * 8;
#pragma unroll
            for (int ni = 0; ni < 4; ni++) {
                int col = c0 + ni * 8;
                *(float2*)(Cg + (size_t)row * N + col) =
                    make_float2(acc[mi][ni][2 * hi], acc[mi][ni][2 * hi + 1]);
            }
        }
    }
}

// ---------------- Launch ----------------------------------------------
extern "C" void kernel_launch(void* const* d_in, const int* in_sizes, int n_in,
                              void* d_out, int out_size) {
    (void)in_sizes; (void)n_in; (void)out_size;
    const float* x  = (const float*)d_in[0];
    const int*   gq = (const int*)  d_in[1];
    const float* gs = (const float*)d_in[2];
    const float* gz = (const float*)d_in[3];
    const int*   uq = (const int*)  d_in[4];
    const float* us = (const float*)d_in[5];
    const float* uz = (const float*)d_in[6];
    const int*   dq = (const int*)  d_in[7];
    const float* ds = (const float*)d_in[8];
    const float* dz = (const float*)d_in[9];
    float* out = (float*)d_out;

    static __half *xh_p, *wg_p, *wu_p, *wd_p, *h_p;
    static bool init_done = false;
    if (!init_done) {
        cudaGetSymbolAddress((void**)&xh_p, g_xh);
        cudaGetSymbolAddress((void**)&wg_p, g_Wg);
        cudaGetSymbolAddress((void**)&wu_p, g_Wu);
        cudaGetSymbolAddress((void**)&wd_p, g_Wd);
        cudaGetSymbolAddress((void**)&h_p,  g_h);
        cudaFuncSetAttribute(gemm_gateup, cudaFuncAttributeMaxDynamicSharedMemorySize, GEMM_SMEM);
        cudaFuncSetAttribute(gemm_down,   cudaFuncAttributeMaxDynamicSharedMemorySize, GEMM_SMEM);
        init_done = true;
    }

    // Prepass: x -> fp16, weights -> dequantized fp16 K-major (transposed)
    cvt_x_kernel<<<(M_DIM * D_DIM) / (256 * 4), 256>>>(x);
    dequant_t_kernel<<<dim3(I_DIM / 32, D_DIM / 32), dim3(32, 8)>>>(gq, gs, gz, wg_p, D_DIM, I_DIM);
    dequant_t_kernel<<<dim3(I_DIM / 32, D_DIM / 32), dim3(32, 8)>>>(uq, us, uz, wu_p, D_DIM, I_DIM);
    dequant_t_kernel<<<dim3(D_DIM / 32, I_DIM / 32), dim3(32, 8)>>>(dq, ds, dz, wd_p, I_DIM, D_DIM);

    // Fused gate+up GEMM with SiLU -> g_h (fp16)
    gemm_gateup<<<dim3(M_DIM / 128, I_DIM / 64), 256, GEMM_SMEM>>>(xh_p, wg_p, wu_p, h_p);
    // out = h @ Wd -> fp32
    gemm_down<<<dim3(M_DIM / 128, D_DIM / 128), 256, GEMM_SMEM>>>(h_p, wd_p, out);
}

// round 16
// speedup vs baseline: 1.5223x; 1.0007x over previous
#include <cuda_runtime.h>
#include <cuda_fp16.h>
#include <cstdint>

// ---------------- Problem dims (fixed by the dataset) ----------------
#define D_DIM 4096
#define I_DIM 11008
#define M_DIM 8192          // 4 * 2048 tokens

// ---------------- Scratch (device globals: allocation-free) ----------
__device__ __half g_xh[(size_t)M_DIM * D_DIM];     //  64 MB  x in fp16 [M, D]
__device__ __half g_Wg[(size_t)I_DIM * D_DIM];     //  90 MB  gate W^T [I, D] (K-major)
__device__ __half g_Wu[(size_t)I_DIM * D_DIM];     //  90 MB  up   W^T [I, D]
__device__ __half g_Wd[(size_t)D_DIM * I_DIM];     //  90 MB  down W^T [D, I]
__device__ __half g_h [(size_t)M_DIM * I_DIM];     // 176 MB  h = silu(gate)*up [M, I]

// ---------------- helpers ----------------------------------------
__device__ __forceinline__ uint32_t smem_u32(const void* p) {
    uint32_t a;
    asm("{ .reg .u64 t; cvta.to.shared.u64 t, %1; cvt.u32.u64 %0, t; }" : "=r"(a) : "l"(p));
    return a;
}
__device__ __forceinline__ void cp16(uint32_t s, const void* g) {
    asm volatile("cp.async.cg.shared.global [%0], [%1], 16;" :: "r"(s), "l"(g));
}
#define CP_COMMIT() asm volatile("cp.async.commit_group;" ::: "memory")
#define CP_WAIT1()  asm volatile("cp.async.wait_group 1;" ::: "memory")

#define LDSM_X4(r, addr) \
    asm volatile("ldmatrix.sync.aligned.m8n8.x4.shared.b16 {%0,%1,%2,%3}, [%4];" \
        : "=r"((r)[0]), "=r"((r)[1]), "=r"((r)[2]), "=r"((r)[3]) : "r"(addr))

__device__ __forceinline__ void mma16816(float* c, const uint32_t* a,
                                         uint32_t b0, uint32_t b1) {
    asm volatile(
        "mma.sync.aligned.m16n8k16.row.col.f32.f16.f16.f32 "
        "{%0,%1,%2,%3}, {%4,%5,%6,%7}, {%8,%9}, {%0,%1,%2,%3};"
        : "+f"(c[0]), "+f"(c[1]), "+f"(c[2]), "+f"(c[3])
        : "r"(a[0]), "r"(a[1]), "r"(a[2]), "r"(a[3]), "r"(b0), "r"(b1));
}

// ---------------- Prepass kernels -------------------------------------
__global__ void cvt_x_kernel(const float* __restrict__ x) {
    size_t i = ((size_t)blockIdx.x * blockDim.x + threadIdx.x) * 4;
    float4 v = *(const float4*)(x + i);
    __half2* o = (__half2*)(g_xh + i);
    o[0] = __floats2half2_rn(v.x, v.y);
    o[1] = __floats2half2_rn(v.z, v.w);
}

// q:[K,N] int32 (0..15), s/z:[K/128,N].  Out: Wt[N,K] fp16, Wt[n,k] = (q[k,n]-8)*s+z
__global__ void dequant_t_kernel(const int* __restrict__ q, const float* __restrict__ s,
                                 const float* __restrict__ z, __half* __restrict__ Wt,
                                 int K, int N) {
    __shared__ __half tile[32][33];
    int n0 = blockIdx.x * 32, k0 = blockIdx.y * 32;
    int tx = threadIdx.x, ty = threadIdx.y;          // block (32, 8)
    int n = n0 + tx;
    int grp = k0 >> 7;                               // whole 32-row tile in one group
    float sv = s[(size_t)grp * N + n];
    float zv = z[(size_t)grp * N + n];
#pragma unroll
    for (int i = 0; i < 4; i++) {
        int k = k0 + ty + i * 8;
        int qv = q[(size_t)k * N + n];
        tile[ty + i * 8][tx] = __float2half((float)(qv - 8) * sv + zv);
    }
    __syncthreads();
#pragma unroll
    for (int i = 0; i < 4; i++) {
        int nn = n0 + ty + i * 8;
        Wt[(size_t)nn * K + k0 + tx] = tile[tx][ty + i * 8];
    }
}

// ---------------- Common GEMM constants --------------------------------
// 144B SMEM row pitch (128B data + 16B pad -> conflict-free ldmatrix),
// 3-stage cp.async, BK=64, 256 threads, __launch_bounds__(256, 2).
static constexpr int ROW_PITCH = 144;
static constexpr int STAGE_B   = 256 * ROW_PITCH;        // 36864 (256 rows/stage)
static constexpr int GEMM_SMEM = 3 * STAGE_B;            // 110592

// ---------------- Fused gate+up GEMM + SiLU ----------------------------
// For one CTA: gate/up tiles of 128(M) x 64(N); B region holds Wg rows then
// Wu rows (64 each).  8 warps = 4(M) x 2(N), warp tile 32x32 per matrix.
// Epilogue: g_h = silu(gate) * up   (fp32 accs -> fp16), no intermediate.
static constexpr int A_ROWS_F  = 128;
static constexpr int A_BYTES_F = A_ROWS_F * ROW_PITCH;   // 18432
static constexpr int BU_OFF_F  = A_BYTES_F + 64 * ROW_PITCH;  // Wu rows after Wg

__global__ void __launch_bounds__(256, 2)
gemm_gateup(const __half* __restrict__ Ag, const __half* __restrict__ Bgg,
            const __half* __restrict__ Bug, __half* __restrict__ Hg) {
    extern __shared__ char smem[];
    uint32_t sb = smem_u32(smem);
    int tid = threadIdx.x;
    int lane = tid & 31, warp = tid >> 5;
    int wm = (warp & 3) * 32;        // warp M offset (0..96)
    int wn = (warp >> 2) * 32;       // warp N offset (0 or 32)
    int m0 = blockIdx.x * 128;
    int n0 = blockIdx.y * 64;
    const int K = D_DIM;

    const __half* gA  = Ag  + (size_t)m0 * K;
    const __half* gBg = Bgg + (size_t)n0 * K;
    const __half* gBu = Bug + (size_t)n0 * K;

    auto load_stage = [&](int s, int k0) {
        uint32_t sa = sb + (uint32_t)s * STAGE_B;
#pragma unroll
        for (int i = 0; i < 4; i++) {                 // A: 128 rows x 128B
            int id = tid + i * 256;
            int r = id >> 3, c = id & 7;
            cp16(sa + r * ROW_PITCH + c * 16, gA + (size_t)r * K + k0 + c * 8);
        }
#pragma unroll
        for (int i = 0; i < 2; i++) {                 // Bg: 64 rows x 128B
            int id = tid + i * 256;
            int r = id >> 3, c = id & 7;
            cp16(sa + A_BYTES_F + r * ROW_PITCH + c * 16, gBg + (size_t)r * K + k0 + c * 8);
        }
#pragma unroll
        for (int i = 0; i < 2; i++) {                 // Bu: 64 rows x 128B
            int id = tid + i * 256;
            int r = id >> 3, c = id & 7;
            cp16(sa + BU_OFF_F + r * ROW_PITCH + c * 16, gBu + (size_t)r * K + k0 + c * 8);
        }
        CP_COMMIT();
    };

    uint32_t a_row = (uint32_t)((wm + (lane & 15)) * ROW_PITCH) + (uint32_t)((lane >> 4) * 16);
    uint32_t b_row = (uint32_t)((wn + (lane & 7) + ((lane >> 4) & 1) * 8) * ROW_PITCH)
                   + (uint32_t)(((lane >> 3) & 1) * 16);

    float accg[2][4][4], accu[2][4][4];
#pragma unroll
    for (int i = 0; i < 2; i++)
#pragma unroll
        for (int j = 0; j < 4; j++)
#pragma unroll
            for (int l = 0; l < 4; l++) { accg[i][j][l] = 0.0f; accu[i][j][l] = 0.0f; }

    load_stage(0, 0);
    load_stage(1, 64);

    const int nk = K / 64;
#pragma unroll 1
    for (int k = 0; k < nk; k++) {
        CP_WAIT1();
        __syncthreads();
        if (k + 2 < nk) {
            load_stage((k + 2) % 3, (k + 2) * 64);
        } else {
            CP_COMMIT();
        }

        uint32_t sa  = sb + (uint32_t)(k % 3) * STAGE_B;
        uint32_t sBg = sa + A_BYTES_F;
        uint32_t sBu = sa + BU_OFF_F;
#pragma unroll
        for (int ks = 0; ks < 4; ks++) {
            uint32_t ko = (uint32_t)(ks * 32);
            uint32_t a[2][4], bg[2][4], bu[2][4];
#pragma unroll
            for (int mi = 0; mi < 2; mi++)
                LDSM_X4(a[mi], sa + a_row + (uint32_t)(mi * 16 * ROW_PITCH) + ko);
#pragma unroll
            for (int bi = 0; bi < 2; bi++) {
                LDSM_X4(bg[bi], sBg + b_row + (uint32_t)(bi * 16 * ROW_PITCH) + ko);
                LDSM_X4(bu[bi], sBu + b_row + (uint32_t)(bi * 16 * ROW_PITCH) + ko);
            }
#pragma unroll
            for (int mi = 0; mi < 2; mi++)
#pragma unroll
                for (int bi = 0; bi < 2; bi++) {
                    mma16816(accg[mi][2 * bi],     a[mi], bg[bi][0], bg[bi][1]);
                    mma16816(accg[mi][2 * bi + 1], a[mi], bg[bi][2], bg[bi][3]);
                    mma16816(accu[mi][2 * bi],     a[mi], bu[bi][0], bu[bi][1]);
                    mma16816(accu[mi][2 * bi + 1], a[mi], bu[bi][2], bu[bi][3]);
                }
        }
    }

    // ---- epilogue: h = silu(gate) * up ----
    int r0 = m0 + wm + (lane >> 2);
    int c0 = n0 + wn + (lane & 3) * 2;
#pragma unroll
    for (int mi = 0; mi < 2; mi++) {
#pragma unroll
        for (int hi = 0; hi < 2; hi++) {
            int row = r0 + mi * 16 + hi * 8;
#pragma unroll
            for (int ni = 0; ni < 4; ni++) {
                int col = c0 + ni * 8;
                float g0 = accg[mi][ni][2 * hi], g1 = accg[mi][ni][2 * hi + 1];
                float u0 = accu[mi][ni][2 * hi], u1 = accu[mi][ni][2 * hi + 1];
                float h0 = g0 / (1.0f + __expf(-g0)) * u0;
                float h1 = g1 / (1.0f + __expf(-g1)) * u1;
                *(__half2*)(Hg + (size_t)row * I_DIM + col) = __floats2half2_rn(h0, h1);
            }
        }
    }
}

// ---------------- Down GEMM: out = h @ Wd^T (fp32 out) -----------------
// CTA tile 128x128, BK=64, 8 warps (2 M x 4 N), warp tile 64x32.
static constexpr int A_BYTES_D = 128 * ROW_PITCH;        // 18432

__global__ void __launch_bounds__(256, 2)
gemm_down(const __half* __restrict__ Ag, const __half* __restrict__ Bg,
          float* __restrict__ Cg) {
    extern __shared__ char smem[];
    uint32_t sb = smem_u32(smem);
    int tid = threadIdx.x;
    int lane = tid & 31, warp = tid >> 5;
    int wm = (warp & 1) * 64;
    int wn = (warp >> 1) * 32;
    int m0 = blockIdx.x * 128;
    int n0 = blockIdx.y * 128;
    const int K = I_DIM, N = D_DIM;

    const __half* gA = Ag + (size_t)m0 * K;
    const __half* gB = Bg + (size_t)n0 * K;

    auto load_stage = [&](int s, int k0) {
        uint32_t sa = sb + (uint32_t)s * STAGE_B;
#pragma unroll
        for (int i = 0; i < 4; i++) {
            int id = tid + i * 256;
            int r = id >> 3, c = id & 7;
            cp16(sa + r * ROW_PITCH + c * 16, gA + (size_t)r * K + k0 + c * 8);
        }
#pragma unroll
        for (int i = 0; i < 4; i++) {
            int id = tid + i * 256;
            int r = id >> 3, c = id & 7;
            cp16(sa + A_BYTES_D + r * ROW_PITCH + c * 16, gB + (size_t)r * K + k0 + c * 8);
        }
        CP_COMMIT();
    };

    uint32_t a_row = (uint32_t)((wm + (lane & 15)) * ROW_PITCH) + (uint32_t)((lane >> 4) * 16);
    uint32_t b_row = (uint32_t)((wn + (lane & 7) + ((lane >> 4) & 1) * 8) * ROW_PITCH)
                   + (uint32_t)(((lane >> 3) & 1) * 16);

    float acc[4][4][4];
#pragma unroll
    for (int i = 0; i < 4; i++)
#pragma unroll
        for (int j = 0; j < 4; j++)
#pragma unroll
            for (int l = 0; l < 4; l++) acc[i][j][l] = 0.0f;

    load_stage(0, 0);
    load_stage(1, 64);

    const int nk = K / 64;
#pragma unroll 1
    for (int k = 0; k < nk; k++) {
        CP_WAIT1();
        __syncthreads();
        if (k + 2 < nk) {
            load_stage((k + 2) % 3, (k + 2) * 64);
        } else {
            CP_COMMIT();
        }

        uint32_t sa = sb + (uint32_t)(k % 3) * STAGE_B;
        uint32_t sB = sa + A_BYTES_D;
#pragma unroll
        for (int ks = 0; ks < 4; ks++) {
            uint32_t ko = (uint32_t)(ks * 32);
            uint32_t a[4][4], b[2][4];
#pragma unroll
            for (int mi = 0; mi < 4; mi++)
                LDSM_X4(a[mi], sa + a_row + (uint32_t)(mi * 16 * ROW_PITCH) + ko);
#pragma unroll
            for (int bi = 0; bi < 2; bi++)
                LDSM_X4(b[bi], sB + b_row + (uint32_t)(bi * 16 * ROW_PITCH) + ko);
#pragma unroll
            for (int mi = 0; mi < 4; mi++)
#pragma unroll
                for (int bi = 0; bi < 2; bi++) {
                    mma16816(acc[mi][2 * bi],     a[mi], b[bi][0], b[bi][1]);
                    mma16816(acc[mi][2 * bi + 1], a[mi], b[bi][2], b[bi][3]);
                }
        }
    }

    int r0 = m0 + wm + (lane >> 2);
    int c0 = n0 + wn + (lane & 3) * 2;
#pragma unroll
    for (int mi = 0; mi < 4; mi++) {
#pragma unroll
        for (int hi = 0; hi < 2; hi++) {
            int row = r0 + mi * 16 + hi * 8;
#pragma unroll
            for (int ni = 0; ni < 4; ni++) {
                int col = c0 + ni * 8;
                *(float2*)(Cg + (size_t)row * N + col) =
                    make_float2(acc[mi][ni][2 * hi], acc[mi][ni][2 * hi + 1]);
            }
        }
    }
}

// ---------------- Launch ----------------------------------------------
extern "C" void kernel_launch(void* const* d_in, const int* in_sizes, int n_in,
                              void* d_out, int out_size) {
    (void)in_sizes; (void)n_in; (void)out_size;
    const float* x  = (const float*)d_in[0];
    const int*   gq = (const int*)  d_in[1];
    const float* gs = (const float*)d_in[2];
    const float* gz = (const float*)d_in[3];
    const int*   uq = (const int*)  d_in[4];
    const float* us = (const float*)d_in[5];
    const float* uz = (const float*)d_in[6];
    const int*   dq = (const int*)  d_in[7];
    const float* ds = (const float*)d_in[8];
    const float* dz = (const float*)d_in[9];
    float* out = (float*)d_out;

    static __half *xh_p, *wg_p, *wu_p, *wd_p, *h_p;
    static cudaStream_t s1, s2, s3;
    static cudaEvent_t e0, eg, eu, ed;
    static bool init_done = false;
    if (!init_done) {
        cudaGetSymbolAddress((void**)&xh_p, g_xh);
        cudaGetSymbolAddress((void**)&wg_p, g_Wg);
        cudaGetSymbolAddress((void**)&wu_p, g_Wu);
        cudaGetSymbolAddress((void**)&wd_p, g_Wd);
        cudaGetSymbolAddress((void**)&h_p,  g_h);
        cudaFuncSetAttribute(gemm_gateup, cudaFuncAttributeMaxDynamicSharedMemorySize, GEMM_SMEM);
        cudaFuncSetAttribute(gemm_down,   cudaFuncAttributeMaxDynamicSharedMemorySize, GEMM_SMEM);
        cudaStreamCreateWithFlags(&s1, cudaStreamNonBlocking);
        cudaStreamCreateWithFlags(&s2, cudaStreamNonBlocking);
        cudaStreamCreateWithFlags(&s3, cudaStreamNonBlocking);
        cudaEventCreateWithFlags(&e0, cudaEventDisableTiming);
        cudaEventCreateWithFlags(&eg, cudaEventDisableTiming);
        cudaEventCreateWithFlags(&eu, cudaEventDisableTiming);
        cudaEventCreateWithFlags(&ed, cudaEventDisableTiming);
        init_done = true;
    }

    // Fork: side streams join the capture graph via an event on the main stream.
    cudaEventRecord(e0, 0);
    cudaStreamWaitEvent(s1, e0, 0);
    cudaStreamWaitEvent(s2, e0, 0);
    cudaStreamWaitEvent(s3, e0, 0);

    // Prepass, concurrent: x conversion on main stream; three dequants on side.
    cvt_x_kernel<<<(M_DIM * D_DIM) / (256 * 4), 256>>>(x);
    dequant_t_kernel<<<dim3(I_DIM / 32, D_DIM / 32), dim3(32, 8), 0, s1>>>(gq, gs, gz, wg_p, D_DIM, I_DIM);
    dequant_t_kernel<<<dim3(I_DIM / 32, D_DIM / 32), dim3(32, 8), 0, s2>>>(uq, us, uz, wu_p, D_DIM, I_DIM);
    dequant_t_kernel<<<dim3(D_DIM / 32, I_DIM / 32), dim3(32, 8), 0, s3>>>(dq, ds, dz, wd_p, I_DIM, D_DIM);
    cudaEventRecord(eg, s1);
    cudaEventRecord(eu, s2);
    cudaEventRecord(ed, s3);

    // GEMM1 needs x, Wg, Wu (Wd dequant keeps running underneath).
    cudaStreamWaitEvent(0, eg, 0);
    cudaStreamWaitEvent(0, eu, 0);
    gemm_gateup<<<dim3(M_DIM / 128, I_DIM / 64), 256, GEMM_SMEM>>>(xh_p, wg_p, wu_p, h_p);

    // GEMM2 additionally needs Wd.
    cudaStreamWaitEvent(0, ed, 0);
    gemm_down<<<dim3(M_DIM / 128, D_DIM / 128), 256, GEMM_SMEM>>>(h_p, wd_p, out);
}